// round 1
// baseline (speedup 1.0000x reference)
#include <cuda_runtime.h>
#include <math.h>

#define H 16
#define S 2048
#define D 1024
#define DH 64
#define RANK 16

// ---------------- scratch (device globals; no allocation allowed) ----------------
__device__ float g_q[H * S * DH];
__device__ float g_k[H * S * DH];
__device__ float g_v[H * S * DH];
__device__ float g_alpha[H * S * DH];
__device__ float g_r[H * S * DH];
__device__ float g_ctx[H * S * DH];
__device__ float g_K[(size_t)H * S * S];        // 256 MB RBF kernel matrix
__device__ float g_qn[H * S];
__device__ float g_kn[H * S];
__device__ float g_diagp[H * S];
__device__ float g_U[H * S * RANK];
__device__ float g_utr_part[8 * H * RANK * DH]; // split-K partials for U^T r

__device__ __forceinline__ float softplusf(float x) {
    return (x > 20.f) ? x : log1pf(expf(x));
}

// ---------------- C = A(2048x1024) @ W(1024x1024) -> heads layout [h][s][dh] ------
__global__ void gemm_xw_heads(const float* __restrict__ A, const float* __restrict__ W,
                              int which) {
    __shared__ float As[16][65];
    __shared__ float Bs[16][65];
    float* outh = (which == 0) ? g_q : (which == 1) ? g_k : g_v;

    int row0 = blockIdx.y * 64;
    int col0 = blockIdx.x * 64;
    int tid = threadIdx.x;
    int tx = tid & 15, ty = tid >> 4;
    float acc[4][4] = {};

    for (int k0 = 0; k0 < D; k0 += 16) {
#pragma unroll
        for (int e = 0; e < 4; e++) {
            int idx = tid + 256 * e;
            int m = idx >> 4, kk = idx & 15;
            As[kk][m] = A[(size_t)(row0 + m) * D + k0 + kk];
            int kb = idx >> 6, n = idx & 63;
            Bs[kb][n] = W[(size_t)(k0 + kb) * D + col0 + n];
        }
        __syncthreads();
#pragma unroll
        for (int kk = 0; kk < 16; kk++) {
            float a[4], b[4];
#pragma unroll
            for (int i = 0; i < 4; i++) a[i] = As[kk][ty * 4 + i];
#pragma unroll
            for (int j = 0; j < 4; j++) b[j] = Bs[kk][tx * 4 + j];
#pragma unroll
            for (int i = 0; i < 4; i++)
#pragma unroll
                for (int j = 0; j < 4; j++) acc[i][j] += a[i] * b[j];
        }
        __syncthreads();
    }
#pragma unroll
    for (int i = 0; i < 4; i++)
#pragma unroll
        for (int j = 0; j < 4; j++) {
            int s = row0 + ty * 4 + i;
            int n = col0 + tx * 4 + j;
            outh[((size_t)(n >> 6) * S + s) * DH + (n & 63)] = acc[i][j];
        }
}

// ---------------- row norms of q and k ----------------
__global__ void norms_kernel() {
    int gw = (blockIdx.x * blockDim.x + threadIdx.x) >> 5;
    int lane = threadIdx.x & 31;
    if (gw >= 2 * H * S) return;
    const float* src = (gw < H * S) ? g_q : g_k;
    float* dst = (gw < H * S) ? g_qn : g_kn;
    int row = (gw < H * S) ? gw : gw - H * S;
    const float* p = src + (size_t)row * DH;
    float a = p[lane], b = p[lane + 32];
    float sum = a * a + b * b;
#pragma unroll
    for (int o = 16; o > 0; o >>= 1) sum += __shfl_xor_sync(0xffffffffu, sum, o);
    if (lane == 0) dst[row] = sum;
}

// ---------------- K[h,i,j] = exp(-max(|q|^2+|k|^2-2 q.k, 0) / (2 bw^2)) -----------
__global__ void kmat_kernel(const float* __restrict__ bw_p) {
    __shared__ float qs[64][DH + 1];
    __shared__ float ks[64][DH + 1];
    __shared__ float qn_s[64], kn_s[64];
    int h = blockIdx.z;
    int i0 = blockIdx.y * 64, j0 = blockIdx.x * 64;
    int tid = threadIdx.x, tx = tid & 15, ty = tid >> 4;
    const float* qb = g_q + (size_t)(h * S + i0) * DH;
    const float* kb = g_k + (size_t)(h * S + j0) * DH;
#pragma unroll
    for (int e = 0; e < 16; e++) {
        int idx = tid + 256 * e;
        int m = idx >> 6, d = idx & 63;
        qs[m][d] = qb[(size_t)m * DH + d];
        ks[m][d] = kb[(size_t)m * DH + d];
    }
    if (tid < 64) qn_s[tid] = g_qn[h * S + i0 + tid];
    else if (tid < 128) kn_s[tid - 64] = g_kn[h * S + j0 + tid - 64];
    __syncthreads();

    float acc[4][4] = {};
#pragma unroll
    for (int d = 0; d < DH; d++) {
        float a[4], b[4];
#pragma unroll
        for (int i = 0; i < 4; i++) a[i] = qs[ty * 4 + i][d];
#pragma unroll
        for (int j = 0; j < 4; j++) b[j] = ks[tx * 4 + j][d];
#pragma unroll
        for (int i = 0; i < 4; i++)
#pragma unroll
            for (int j = 0; j < 4; j++) acc[i][j] += a[i] * b[j];
    }
    float bw = softplusf(bw_p[0]) + 1e-6f;
    float inv = 1.0f / (2.0f * bw * bw);
    float* Kout = g_K + ((size_t)h * S + i0) * S + j0;
#pragma unroll
    for (int i = 0; i < 4; i++)
#pragma unroll
        for (int j = 0; j < 4; j++) {
            float dist = qn_s[ty * 4 + i] + kn_s[tx * 4 + j] - 2.0f * acc[i][j];
            dist = fmaxf(dist, 0.0f);
            Kout[(size_t)(ty * 4 + i) * S + tx * 4 + j] = __expf(-dist * inv);
        }
}

// ---------------- diag_p = softplus(diag(K)) * diag_scale + reg -------------------
__global__ void diagp_kernel(const float* __restrict__ diag_scale,
                             const float* __restrict__ reg_p) {
    int i = blockIdx.x * blockDim.x + threadIdx.x;
    if (i >= H * S) return;
    int h = i / S, s = i - h * S;
    float kd = g_K[((size_t)h * S + s) * S + s];
    g_diagp[i] = softplusf(kd) * diag_scale[h] + reg_p[0];
}

// ---------------- U[h,s,r] = sum_rp pos[s,rp] * proj[h,rp,r] ----------------------
__global__ void u_kernel(const float* __restrict__ pos, const float* __restrict__ proj) {
    __shared__ float pr[RANK][RANK];
    int h = blockIdx.y;
    int tid = threadIdx.x; // 256
    pr[tid >> 4][tid & 15] = proj[h * RANK * RANK + tid];
    __syncthreads();
    int s = blockIdx.x * 256 + tid;
    float pe[RANK];
#pragma unroll
    for (int r = 0; r < RANK; r++) pe[r] = pos[(size_t)s * RANK + r];
#pragma unroll
    for (int r = 0; r < RANK; r++) {
        float acc = 0.f;
#pragma unroll
        for (int rp = 0; rp < RANK; rp++) acc += pe[rp] * pr[rp][r];
        g_U[((size_t)h * S + s) * RANK + r] = acc;
    }
}

// ---------------- alpha = 0; r = v (first Richardson iteration shortcut) ----------
__global__ void init_kernel() {
    int i = blockIdx.x * blockDim.x + threadIdx.x;
    if (i < H * S * DH) {
        g_alpha[i] = 0.0f;
        g_r[i] = g_v[i];
    }
}

// ---------------- acc = K @ alpha; mode0: r = v - acc - lam*alpha; mode1: ctx=acc -
__global__ void kapply_kernel(int mode, const float* __restrict__ lam_p) {
    __shared__ float Ks[64][65];
    __shared__ float Al[64][65];
    int h = blockIdx.y;
    int r0 = blockIdx.x * 64;
    int tid = threadIdx.x, tx = tid & 15, ty = tid >> 4;
    const float* Kb = g_K + ((size_t)h * S + r0) * S;
    const float* Ab = g_alpha + (size_t)h * S * DH;
    float acc[4][4] = {};

    for (int t0 = 0; t0 < S; t0 += 64) {
#pragma unroll
        for (int e = 0; e < 16; e++) {
            int idx = tid + 256 * e;
            int m = idx >> 6, c = idx & 63;
            Ks[m][c] = Kb[(size_t)m * S + t0 + c];
            Al[m][c] = Ab[(size_t)(t0 + m) * DH + c];
        }
        __syncthreads();
#pragma unroll
        for (int tt = 0; tt < 64; tt++) {
            float a[4], b[4];
#pragma unroll
            for (int i = 0; i < 4; i++) a[i] = Ks[ty * 4 + i][tt];
#pragma unroll
            for (int j = 0; j < 4; j++) b[j] = Al[tt][tx * 4 + j];
#pragma unroll
            for (int i = 0; i < 4; i++)
#pragma unroll
                for (int j = 0; j < 4; j++) acc[i][j] += a[i] * b[j];
        }
        __syncthreads();
    }

    float lam = softplusf(lam_p[0]);
#pragma unroll
    for (int i = 0; i < 4; i++)
#pragma unroll
        for (int j = 0; j < 4; j++) {
            int s = r0 + ty * 4 + i;
            int d = tx * 4 + j;
            size_t idx = ((size_t)h * S + s) * DH + d;
            if (mode == 0)
                g_r[idx] = g_v[idx] - acc[i][j] - lam * g_alpha[idx];
            else
                g_ctx[idx] = acc[i][j];
        }
}

// ---------------- utr_part[p,h,r,d] = sum_{s in part} U[h,s,r] * r[h,s,d] ---------
__global__ void utr_kernel() {
    int h = blockIdx.x;
    int part = blockIdx.y;
    int tid = threadIdx.x; // 1024
    int d = tid & 63, rr = tid >> 6;
    const float* Ub = g_U + (size_t)h * S * RANK;
    const float* rb = g_r + (size_t)h * S * DH;
    int s0 = part * (S / 8);
    float a0 = 0, a1 = 0, a2 = 0, a3 = 0;
    for (int s = s0; s < s0 + S / 8; s += 4) {
        a0 += Ub[(s + 0) * RANK + rr] * rb[(size_t)(s + 0) * DH + d];
        a1 += Ub[(s + 1) * RANK + rr] * rb[(size_t)(s + 1) * DH + d];
        a2 += Ub[(s + 2) * RANK + rr] * rb[(size_t)(s + 2) * DH + d];
        a3 += Ub[(s + 3) * RANK + rr] * rb[(size_t)(s + 3) * DH + d];
    }
    g_utr_part[((part * H + h) * RANK + rr) * DH + d] = (a0 + a1) + (a2 + a3);
}

// ---------------- alpha += r*diag_p + U @ utr -------------------------------------
__global__ void update_kernel() {
    __shared__ float ut[RANK][DH];
    __shared__ float Us[16][RANK];
    int h = blockIdx.y;
    int tid = threadIdx.x; // 1024
    {
        float sum = 0.f;
#pragma unroll
        for (int p = 0; p < 8; p++) sum += g_utr_part[(p * H + h) * RANK * DH + tid];
        ut[tid >> 6][tid & 63] = sum;
    }
    int s0 = blockIdx.x * 16;
    if (tid < 16 * RANK)
        Us[tid >> 4][tid & 15] = g_U[((size_t)h * S + s0 + (tid >> 4)) * RANK + (tid & 15)];
    __syncthreads();

    int sl = tid >> 6;
    int d = tid & 63;
    int s = s0 + sl;
    size_t idx = ((size_t)h * S + s) * DH + d;
    float acc = 0.f;
#pragma unroll
    for (int r2 = 0; r2 < RANK; r2++) acc += Us[sl][r2] * ut[r2][d];
    g_alpha[idx] += g_r[idx] * g_diagp[h * S + s] + acc;
}

// ---------------- out[s,n] = sum_k ctx_flat[s,k] * Wo[k,n] ------------------------
__global__ void gemm_ctx_wo(const float* __restrict__ Wo, float* __restrict__ out) {
    __shared__ float As[16][65];
    __shared__ float Bs[16][65];
    int row0 = blockIdx.y * 64;
    int col0 = blockIdx.x * 64;
    int tid = threadIdx.x, tx = tid & 15, ty = tid >> 4;
    float acc[4][4] = {};

    for (int k0 = 0; k0 < D; k0 += 16) {
#pragma unroll
        for (int e = 0; e < 4; e++) {
            int idx = tid + 256 * e;
            int m = idx >> 4, kk = idx & 15;
            int gk = k0 + kk;
            As[kk][m] = g_ctx[((size_t)(gk >> 6) * S + row0 + m) * DH + (gk & 63)];
            int kb = idx >> 6, n = idx & 63;
            Bs[kb][n] = Wo[(size_t)(k0 + kb) * D + col0 + n];
        }
        __syncthreads();
#pragma unroll
        for (int kk = 0; kk < 16; kk++) {
            float a[4], b[4];
#pragma unroll
            for (int i = 0; i < 4; i++) a[i] = As[kk][ty * 4 + i];
#pragma unroll
            for (int j = 0; j < 4; j++) b[j] = Bs[kk][tx * 4 + j];
#pragma unroll
            for (int i = 0; i < 4; i++)
#pragma unroll
                for (int j = 0; j < 4; j++) acc[i][j] += a[i] * b[j];
        }
        __syncthreads();
    }
#pragma unroll
    for (int i = 0; i < 4; i++)
#pragma unroll
        for (int j = 0; j < 4; j++) {
            int s = row0 + ty * 4 + i;
            int n = col0 + tx * 4 + j;
            out[(size_t)s * D + n] = acc[i][j];
        }
}

// ---------------- launch ----------------------------------------------------------
extern "C" void kernel_launch(void* const* d_in, const int* in_sizes, int n_in,
                              void* d_out, int out_size) {
    const float* x          = (const float*)d_in[0];
    const float* Wq         = (const float*)d_in[1];
    const float* Wk         = (const float*)d_in[2];
    const float* Wv         = (const float*)d_in[3];
    const float* Wo         = (const float*)d_in[4];
    const float* bandwidth  = (const float*)d_in[5];
    const float* diag_scale = (const float*)d_in[6];
    const float* pos        = (const float*)d_in[7];
    const float* proj       = (const float*)d_in[8];
    const float* reg        = (const float*)d_in[9];
    const float* lam        = (const float*)d_in[10];
    float* out = (float*)d_out;

    dim3 gemmGrid(D / 64, S / 64); // (16, 32)
    gemm_xw_heads<<<gemmGrid, 256>>>(x, Wq, 0);
    gemm_xw_heads<<<gemmGrid, 256>>>(x, Wk, 1);
    gemm_xw_heads<<<gemmGrid, 256>>>(x, Wv, 2);

    norms_kernel<<<(2 * H * S * 32 + 255) / 256, 256>>>();
    kmat_kernel<<<dim3(S / 64, S / 64, H), 256>>>(bandwidth);
    diagp_kernel<<<(H * S + 255) / 256, 256>>>(diag_scale, reg);
    u_kernel<<<dim3(S / 256, H), 256>>>(pos, proj);

    // Richardson iteration 1: alpha = 0 => r = v
    init_kernel<<<(H * S * DH + 255) / 256, 256>>>();
    utr_kernel<<<dim3(H, 8), 1024>>>();
    update_kernel<<<dim3(S / 16, H), 1024>>>();

    // iterations 2..5
    for (int it = 1; it < 5; it++) {
        kapply_kernel<<<dim3(S / 64, H), 256>>>(0, lam);
        utr_kernel<<<dim3(H, 8), 1024>>>();
        update_kernel<<<dim3(S / 16, H), 1024>>>();
    }

    // out = K @ alpha, then @ Wo
    kapply_kernel<<<dim3(S / 64, H), 256>>>(1, lam);
    gemm_ctx_wo<<<dim3(D / 64, S / 64), 256>>>(Wo, out);
}

// round 4
// speedup vs baseline: 1.8311x; 1.8311x over previous
#include <cuda_runtime.h>
#include <cuda_fp16.h>
#include <math.h>
#include <cstdint>

#define H 16
#define S 2048
#define D 1024
#define DH 64
#define RANK 16

// ---------------- scratch (device globals; no allocation allowed) ----------------
__device__ float g_q[H * S * DH];
__device__ float g_k[H * S * DH];
__device__ float g_v[H * S * DH];
__device__ float g_alpha[H * S * DH];
__device__ __half g_alphaH[H * S * DH];          // fp16 mirror of alpha for MMA B operand
__device__ float g_r[H * S * DH];
__device__ float g_ctx[H * S * DH];
__device__ float g_dist[(size_t)H * S * S];      // 256 MB fp32 dist^2
__device__ __half g_Kh[(size_t)H * S * S];       // 128 MB fp16 row-normalized kernel
__device__ unsigned g_rowmin[H * S];             // per-row min dist (bit-ordered)
__device__ float g_scale[H * S];                 // per-row scale exp(-dmin*inv)
__device__ float g_qn[H * S];
__device__ float g_kn[H * S];
__device__ float g_diagp[H * S];
__device__ float g_U[H * S * RANK];
__device__ float g_utr_part[8 * H * RANK * DH]; // split-K partials for U^T r

__device__ __forceinline__ float softplusf(float x) {
    return (x > 20.f) ? x : log1pf(expf(x));
}

// ======================= HMMA helpers (mma.sync + ldmatrix) =======================
__device__ __forceinline__ uint32_t smem_u32(const void* p) {
    uint32_t a;
    asm("{ .reg .u64 t; cvta.to.shared.u64 t, %1; cvt.u32.u64 %0, t; }" : "=r"(a) : "l"(p));
    return a;
}
__device__ __forceinline__ void ldm_x4(uint32_t* r, uint32_t addr) {
    asm volatile("ldmatrix.sync.aligned.m8n8.x4.shared.b16 {%0,%1,%2,%3}, [%4];"
                 : "=r"(r[0]), "=r"(r[1]), "=r"(r[2]), "=r"(r[3]) : "r"(addr));
}
__device__ __forceinline__ void ldm_x4_trans(uint32_t* r, uint32_t addr) {
    asm volatile("ldmatrix.sync.aligned.m8n8.x4.trans.shared.b16 {%0,%1,%2,%3}, [%4];"
                 : "=r"(r[0]), "=r"(r[1]), "=r"(r[2]), "=r"(r[3]) : "r"(addr));
}
__device__ __forceinline__ void mma16816(float* c, const uint32_t* a, uint32_t b0, uint32_t b1) {
    asm volatile(
        "mma.sync.aligned.m16n8k16.row.col.f32.f16.f16.f32 "
        "{%0,%1,%2,%3}, {%4,%5,%6,%7}, {%8,%9}, {%0,%1,%2,%3};"
        : "+f"(c[0]), "+f"(c[1]), "+f"(c[2]), "+f"(c[3])
        : "r"(a[0]), "r"(a[1]), "r"(a[2]), "r"(a[3]), "r"(b0), "r"(b1));
}

// ---------------- C = A(2048x1024) @ W(1024x1024) -> heads layout [h][s][dh] ------
__global__ void gemm_xw_heads(const float* __restrict__ A, const float* __restrict__ W,
                              int which) {
    __shared__ float As[16][65];
    __shared__ float Bs[16][65];
    float* outh = (which == 0) ? g_q : (which == 1) ? g_k : g_v;

    int row0 = blockIdx.y * 64;
    int col0 = blockIdx.x * 64;
    int tid = threadIdx.x;
    int tx = tid & 15, ty = tid >> 4;
    float acc[4][4] = {};

    for (int k0 = 0; k0 < D; k0 += 16) {
#pragma unroll
        for (int e = 0; e < 4; e++) {
            int idx = tid + 256 * e;
            int m = idx >> 4, kk = idx & 15;
            As[kk][m] = A[(size_t)(row0 + m) * D + k0 + kk];
            int kb = idx >> 6, n = idx & 63;
            Bs[kb][n] = W[(size_t)(k0 + kb) * D + col0 + n];
        }
        __syncthreads();
#pragma unroll
        for (int kk = 0; kk < 16; kk++) {
            float a[4], b[4];
#pragma unroll
            for (int i = 0; i < 4; i++) a[i] = As[kk][ty * 4 + i];
#pragma unroll
            for (int j = 0; j < 4; j++) b[j] = Bs[kk][tx * 4 + j];
#pragma unroll
            for (int i = 0; i < 4; i++)
#pragma unroll
                for (int j = 0; j < 4; j++) acc[i][j] += a[i] * b[j];
        }
        __syncthreads();
    }
#pragma unroll
    for (int i = 0; i < 4; i++)
#pragma unroll
        for (int j = 0; j < 4; j++) {
            int s = row0 + ty * 4 + i;
            int n = col0 + tx * 4 + j;
            outh[((size_t)(n >> 6) * S + s) * DH + (n & 63)] = acc[i][j];
        }
}

// ---------------- row norms of q and k ----------------
__global__ void norms_kernel() {
    int gw = (blockIdx.x * blockDim.x + threadIdx.x) >> 5;
    int lane = threadIdx.x & 31;
    if (gw >= 2 * H * S) return;
    const float* src = (gw < H * S) ? g_q : g_k;
    float* dst = (gw < H * S) ? g_qn : g_kn;
    int row = (gw < H * S) ? gw : gw - H * S;
    const float* p = src + (size_t)row * DH;
    float a = p[lane], b = p[lane + 32];
    float sum = a * a + b * b;
#pragma unroll
    for (int o = 16; o > 0; o >>= 1) sum += __shfl_xor_sync(0xffffffffu, sum, o);
    if (lane == 0) dst[row] = sum;
}

// ---------------- init rowmin to +inf (every launch) ------------------------------
__global__ void rowmin_init_kernel() {
    int i = blockIdx.x * blockDim.x + threadIdx.x;
    if (i < H * S) g_rowmin[i] = 0x7F800000u;
}

// ---------------- pass A: dist[h,i,j] = max(|q|^2+|k|^2-2 q.k, 0); track row min ---
__global__ void kmat_kernel() {
    __shared__ float qs[64][DH + 1];
    __shared__ float ks[64][DH + 1];
    __shared__ float qn_s[64], kn_s[64];
    int h = blockIdx.z;
    int i0 = blockIdx.y * 64, j0 = blockIdx.x * 64;
    int tid = threadIdx.x, tx = tid & 15, ty = tid >> 4;
    const float* qb = g_q + (size_t)(h * S + i0) * DH;
    const float* kb = g_k + (size_t)(h * S + j0) * DH;
#pragma unroll
    for (int e = 0; e < 16; e++) {
        int idx = tid + 256 * e;
        int m = idx >> 6, d = idx & 63;
        qs[m][d] = qb[(size_t)m * DH + d];
        ks[m][d] = kb[(size_t)m * DH + d];
    }
    if (tid < 64) qn_s[tid] = g_qn[h * S + i0 + tid];
    else if (tid < 128) kn_s[tid - 64] = g_kn[h * S + j0 + tid - 64];
    __syncthreads();

    float acc[4][4] = {};
#pragma unroll
    for (int d = 0; d < DH; d++) {
        float a[4], b[4];
#pragma unroll
        for (int i = 0; i < 4; i++) a[i] = qs[ty * 4 + i][d];
#pragma unroll
        for (int j = 0; j < 4; j++) b[j] = ks[tx * 4 + j][d];
#pragma unroll
        for (int i = 0; i < 4; i++)
#pragma unroll
            for (int j = 0; j < 4; j++) acc[i][j] += a[i] * b[j];
    }
    float* Dout = g_dist + ((size_t)h * S + i0) * S + j0;
    float rmin[4];
#pragma unroll
    for (int i = 0; i < 4; i++) {
        rmin[i] = 3.4e38f;
#pragma unroll
        for (int j = 0; j < 4; j++) {
            float dist = qn_s[ty * 4 + i] + kn_s[tx * 4 + j] - 2.0f * acc[i][j];
            dist = fmaxf(dist, 0.0f);
            Dout[(size_t)(ty * 4 + i) * S + tx * 4 + j] = dist;
            rmin[i] = fminf(rmin[i], dist);
        }
    }
    // reduce min across tx (16 lanes within half-warp)
#pragma unroll
    for (int o = 8; o > 0; o >>= 1)
#pragma unroll
        for (int i = 0; i < 4; i++)
            rmin[i] = fminf(rmin[i], __shfl_xor_sync(0xffffffffu, rmin[i], o));
    if (tx == 0) {
#pragma unroll
        for (int i = 0; i < 4; i++)
            atomicMin(&g_rowmin[h * S + i0 + ty * 4 + i], __float_as_uint(rmin[i]));
    }
}

// ---------------- pass B: Kh[h,i,j] = exp(-(d - dmin_i)*inv) fp16 -----------------
__global__ void kexp_kernel(const float* __restrict__ bw_p) {
    int row = blockIdx.x;   // 0..S-1
    int h = blockIdx.y;
    int t = threadIdx.x;    // 256
    float bw = softplusf(bw_p[0]) + 1e-6f;
    float inv = 1.0f / (2.0f * bw * bw);
    float dmin = __uint_as_float(g_rowmin[h * S + row]);
    const float* Drow = g_dist + ((size_t)h * S + row) * S;
    __half* Krow = g_Kh + ((size_t)h * S + row) * S;
#pragma unroll
    for (int e = 0; e < 8; e++) {
        int j = t + 256 * e;
        Krow[j] = __float2half(__expf(-(Drow[j] - dmin) * inv));
    }
}

// ------- diag_p = softplus(exp(-d_ii*inv)) * diag_scale + reg; also row scale -----
__global__ void diagp_kernel(const float* __restrict__ diag_scale,
                             const float* __restrict__ reg_p,
                             const float* __restrict__ bw_p) {
    int i = blockIdx.x * blockDim.x + threadIdx.x;
    if (i >= H * S) return;
    int h = i / S, s = i - h * S;
    float bw = softplusf(bw_p[0]) + 1e-6f;
    float inv = 1.0f / (2.0f * bw * bw);
    float d_ii = g_dist[((size_t)h * S + s) * S + s];
    float kd = __expf(-d_ii * inv);
    g_diagp[i] = softplusf(kd) * diag_scale[h] + reg_p[0];
    g_scale[i] = __expf(-__uint_as_float(g_rowmin[i]) * inv);
}

// ---------------- U[h,s,r] = sum_rp pos[s,rp] * proj[h,rp,r] ----------------------
__global__ void u_kernel(const float* __restrict__ pos, const float* __restrict__ proj) {
    __shared__ float pr[RANK][RANK];
    int h = blockIdx.y;
    int tid = threadIdx.x; // 256
    pr[tid >> 4][tid & 15] = proj[h * RANK * RANK + tid];
    __syncthreads();
    int s = blockIdx.x * 256 + tid;
    float pe[RANK];
#pragma unroll
    for (int r = 0; r < RANK; r++) pe[r] = pos[(size_t)s * RANK + r];
#pragma unroll
    for (int r = 0; r < RANK; r++) {
        float acc = 0.f;
#pragma unroll
        for (int rp = 0; rp < RANK; rp++) acc += pe[rp] * pr[rp][r];
        g_U[((size_t)h * S + s) * RANK + r] = acc;
    }
}

// ---------------- alpha = 0; r = v (first Richardson iteration shortcut) ----------
__global__ void init_kernel() {
    int i = blockIdx.x * blockDim.x + threadIdx.x;
    if (i < H * S * DH) {
        g_alpha[i] = 0.0f;
        g_r[i] = g_v[i];
    }
}

// ======== HMMA K@alpha: acc = scale * K'@alpha; mode0: r=v-acc-lam*a; 1: ctx=acc ==
__global__ void __launch_bounds__(256) kapply_mma(int mode, const float* __restrict__ lam_p) {
    __shared__ __half Ks[128][72];   // [m][k] tile of K'
    __shared__ __half Al[64][72];    // [t][d] tile of alpha (fp16)

    int tid = threadIdx.x, wid = tid >> 5, lane = tid & 31;
    int h = blockIdx.y;
    int s0 = blockIdx.x * 128;

    const __half* Kb = g_Kh + ((size_t)h * S + s0) * S;
    const __half* Ab = g_alphaH + (size_t)h * S * DH;

    float acc[8][4];
#pragma unroll
    for (int i = 0; i < 8; i++)
#pragma unroll
        for (int j = 0; j < 4; j++) acc[i][j] = 0.f;

    uint32_t ks_base = smem_u32(&Ks[0][0]);
    uint32_t al_base = smem_u32(&Al[0][0]);
    int lm = lane & 15, lh = lane >> 4;  // ldmatrix row-sel / half-sel

    for (int t0 = 0; t0 < S; t0 += 64) {
        // load K tile: 128 rows x 64 cols fp16 (8 uint4 per row)
#pragma unroll
        for (int e = 0; e < 4; e++) {
            int idx = tid + 256 * e;          // 0..1023
            int m = idx >> 3, c8 = idx & 7;
            *(uint4*)&Ks[m][c8 * 8] = *(const uint4*)(Kb + (size_t)m * S + t0 + c8 * 8);
        }
        // load alpha tile: 64 rows x 64 cols fp16
#pragma unroll
        for (int e = 0; e < 2; e++) {
            int idx = tid + 256 * e;          // 0..511
            int t = idx >> 3, c8 = idx & 7;
            *(uint4*)&Al[t][c8 * 8] = *(const uint4*)(Ab + (size_t)(t0 + t) * DH + c8 * 8);
        }
        __syncthreads();

#pragma unroll
        for (int kk = 0; kk < 64; kk += 16) {
            uint32_t a[4];
            ldm_x4(a, ks_base + ((wid * 16 + lm) * 72 + kk + lh * 8) * 2);
#pragma unroll
            for (int nt = 0; nt < 4; nt++) {
                uint32_t b[4];
                ldm_x4_trans(b, al_base + ((kk + lm) * 72 + nt * 16 + lh * 8) * 2);
                mma16816(acc[nt * 2 + 0], a, b[0], b[1]);
                mma16816(acc[nt * 2 + 1], a, b[2], b[3]);
            }
        }
        __syncthreads();
    }

    // epilogue: C frag m16n8: c0/c1 -> row lane/4, cols (lane%4)*2+{0,1}; c2/c3 -> +8
    float lam = 0.f;
    if (mode == 0) lam = softplusf(lam_p[0]);
    int rbase = s0 + wid * 16 + (lane >> 2);
    float sc0 = g_scale[h * S + rbase];
    float sc1 = g_scale[h * S + rbase + 8];
#pragma unroll
    for (int nt = 0; nt < 8; nt++) {
        int col = nt * 8 + (lane & 3) * 2;
        size_t g0 = ((size_t)h * S + rbase) * DH + col;
        size_t g1 = g0 + 8 * DH;
        if (mode == 0) {
            float2 v0 = *(const float2*)&g_v[g0];
            float2 v1 = *(const float2*)&g_v[g1];
            float2 a0 = *(const float2*)&g_alpha[g0];
            float2 a1 = *(const float2*)&g_alpha[g1];
            float2 r0 = make_float2(v0.x - sc0 * acc[nt][0] - lam * a0.x,
                                    v0.y - sc0 * acc[nt][1] - lam * a0.y);
            float2 r1 = make_float2(v1.x - sc1 * acc[nt][2] - lam * a1.x,
                                    v1.y - sc1 * acc[nt][3] - lam * a1.y);
            *(float2*)&g_r[g0] = r0;
            *(float2*)&g_r[g1] = r1;
        } else {
            *(float2*)&g_ctx[g0] = make_float2(sc0 * acc[nt][0], sc0 * acc[nt][1]);
            *(float2*)&g_ctx[g1] = make_float2(sc1 * acc[nt][2], sc1 * acc[nt][3]);
        }
    }
}

// ---------------- utr_part[p,h,r,d] = sum_{s in part} U[h,s,r] * r[h,s,d] ---------
__global__ void utr_kernel() {
    int h = blockIdx.x;
    int part = blockIdx.y;
    int tid = threadIdx.x; // 1024
    int d = tid & 63, rr = tid >> 6;
    const float* Ub = g_U + (size_t)h * S * RANK;
    const float* rb = g_r + (size_t)h * S * DH;
    int s0 = part * (S / 8);
    float a0 = 0, a1 = 0, a2 = 0, a3 = 0;
    for (int s = s0; s < s0 + S / 8; s += 4) {
        a0 += Ub[(s + 0) * RANK + rr] * rb[(size_t)(s + 0) * DH + d];
        a1 += Ub[(s + 1) * RANK + rr] * rb[(size_t)(s + 1) * DH + d];
        a2 += Ub[(s + 2) * RANK + rr] * rb[(size_t)(s + 2) * DH + d];
        a3 += Ub[(s + 3) * RANK + rr] * rb[(size_t)(s + 3) * DH + d];
    }
    g_utr_part[((part * H + h) * RANK + rr) * DH + d] = (a0 + a1) + (a2 + a3);
}

// ---------------- alpha += r*diag_p + U @ utr; also emit fp16 mirror --------------
__global__ void update_kernel() {
    __shared__ float ut[RANK][DH];
    __shared__ float Us[16][RANK];
    int h = blockIdx.y;
    int tid = threadIdx.x; // 1024
    {
        float sum = 0.f;
#pragma unroll
        for (int p = 0; p < 8; p++) sum += g_utr_part[(p * H + h) * RANK * DH + tid];
        ut[tid >> 6][tid & 63] = sum;
    }
    int s0 = blockIdx.x * 16;
    if (tid < 16 * RANK)
        Us[tid >> 4][tid & 15] = g_U[((size_t)h * S + s0 + (tid >> 4)) * RANK + (tid & 15)];
    __syncthreads();

    int sl = tid >> 6;
    int d = tid & 63;
    int s = s0 + sl;
    size_t idx = ((size_t)h * S + s) * DH + d;
    float acc = 0.f;
#pragma unroll
    for (int r2 = 0; r2 < RANK; r2++) acc += Us[sl][r2] * ut[r2][d];
    float na = g_alpha[idx] + g_r[idx] * g_diagp[h * S + s] + acc;
    g_alpha[idx] = na;
    g_alphaH[idx] = __float2half(na);
}

// ---------------- out[s,n] = sum_k ctx_flat[s,k] * Wo[k,n] ------------------------
__global__ void gemm_ctx_wo(const float* __restrict__ Wo, float* __restrict__ out) {
    __shared__ float As[16][65];
    __shared__ float Bs[16][65];
    int row0 = blockIdx.y * 64;
    int col0 = blockIdx.x * 64;
    int tid = threadIdx.x, tx = tid & 15, ty = tid >> 4;
    float acc[4][4] = {};

    for (int k0 = 0; k0 < D; k0 += 16) {
#pragma unroll
        for (int e = 0; e < 4; e++) {
            int idx = tid + 256 * e;
            int m = idx >> 4, kk = idx & 15;
            int gk = k0 + kk;
            As[kk][m] = g_ctx[((size_t)(gk >> 6) * S + row0 + m) * DH + (gk & 63)];
            int kb = idx >> 6, n = idx & 63;
            Bs[kb][n] = Wo[(size_t)(k0 + kb) * D + col0 + n];
        }
        __syncthreads();
#pragma unroll
        for (int kk = 0; kk < 16; kk++) {
            float a[4], b[4];
#pragma unroll
            for (int i = 0; i < 4; i++) a[i] = As[kk][ty * 4 + i];
#pragma unroll
            for (int j = 0; j < 4; j++) b[j] = Bs[kk][tx * 4 + j];
#pragma unroll
            for (int i = 0; i < 4; i++)
#pragma unroll
                for (int j = 0; j < 4; j++) acc[i][j] += a[i] * b[j];
        }
        __syncthreads();
    }
#pragma unroll
    for (int i = 0; i < 4; i++)
#pragma unroll
        for (int j = 0; j < 4; j++) {
            int s = row0 + ty * 4 + i;
            int n = col0 + tx * 4 + j;
            out[(size_t)s * D + n] = acc[i][j];
        }
}

// ---------------- launch ----------------------------------------------------------
extern "C" void kernel_launch(void* const* d_in, const int* in_sizes, int n_in,
                              void* d_out, int out_size) {
    const float* x          = (const float*)d_in[0];
    const float* Wq         = (const float*)d_in[1];
    const float* Wk         = (const float*)d_in[2];
    const float* Wv         = (const float*)d_in[3];
    const float* Wo         = (const float*)d_in[4];
    const float* bandwidth  = (const float*)d_in[5];
    const float* diag_scale = (const float*)d_in[6];
    const float* pos        = (const float*)d_in[7];
    const float* proj       = (const float*)d_in[8];
    const float* reg        = (const float*)d_in[9];
    const float* lam        = (const float*)d_in[10];
    float* out = (float*)d_out;

    dim3 gemmGrid(D / 64, S / 64); // (16, 32)
    gemm_xw_heads<<<gemmGrid, 256>>>(x, Wq, 0);
    gemm_xw_heads<<<gemmGrid, 256>>>(x, Wk, 1);
    gemm_xw_heads<<<gemmGrid, 256>>>(x, Wv, 2);

    norms_kernel<<<(2 * H * S * 32 + 255) / 256, 256>>>();
    rowmin_init_kernel<<<(H * S + 255) / 256, 256>>>();
    kmat_kernel<<<dim3(S / 64, S / 64, H), 256>>>();
    kexp_kernel<<<dim3(S, H), 256>>>(bandwidth);
    diagp_kernel<<<(H * S + 255) / 256, 256>>>(diag_scale, reg, bandwidth);
    u_kernel<<<dim3(S / 256, H), 256>>>(pos, proj);

    // Richardson iteration 1: alpha = 0 => r = v
    init_kernel<<<(H * S * DH + 255) / 256, 256>>>();
    utr_kernel<<<dim3(H, 8), 1024>>>();
    update_kernel<<<dim3(S / 16, H), 1024>>>();

    // iterations 2..5
    for (int it = 1; it < 5; it++) {
        kapply_mma<<<dim3(S / 128, H), 256>>>(0, lam);
        utr_kernel<<<dim3(H, 8), 1024>>>();
        update_kernel<<<dim3(S / 16, H), 1024>>>();
    }

    // out = K @ alpha, then @ Wo
    kapply_mma<<<dim3(S / 128, H), 256>>>(1, lam);
    gemm_ctx_wo<<<dim3(D / 64, S / 64), 256>>>(Wo, out);
}

// round 6
// speedup vs baseline: 3.1914x; 1.7429x over previous
#include <cuda_runtime.h>
#include <cuda_fp16.h>
#include <math.h>
#include <cstdint>

#define H 16
#define S 2048
#define D 1024
#define DH 64
#define RANK 16

// ---------------- scratch (device globals; no allocation allowed) ----------------
__device__ float g_q[H * S * DH];
__device__ float g_k[H * S * DH];
__device__ float g_v[H * S * DH];
__device__ float g_alpha[H * S * DH];
__device__ __half g_alphaH[H * S * DH];
__device__ float g_r[H * S * DH];
__device__ __half g_ctxH[H * S * DH];   // normalized ctx = K'@alpha (hi)
__device__ __half g_ctxL[H * S * DH];   // normalized ctx (lo)
__device__ __half g_Kh[(size_t)H * S * S];       // 128 MB fp16 row-normalized kernel
__device__ float g_scale[H * S];                 // per-row scale exp(-dmin*inv)
__device__ float g_qn[H * S];
__device__ float g_kn[H * S];
__device__ float g_diagp[H * S];
__device__ float g_U[H * S * RANK];
__device__ float g_utr_part[8 * H * RANK * DH];

// split fp16 operands
__device__ __half g_xh[S * D],  g_xl[S * D];
__device__ __half g_Wh[3 * D * D], g_Wl[3 * D * D];   // Wq, Wk, Wv
__device__ __half g_Woh[D * D], g_Wol[D * D];
__device__ __half g_qhh[H * S * DH], g_qll[H * S * DH];
__device__ __half g_khh[H * S * DH], g_kll[H * S * DH];
__device__ __half g_kTh[H * DH * S], g_kTl[H * DH * S];  // transposed k

__device__ __forceinline__ float softplusf(float x) {
    return (x > 20.f) ? x : log1pf(expf(x));
}

// ======================= HMMA helpers (mma.sync + ldmatrix) =======================
__device__ __forceinline__ uint32_t smem_u32(const void* p) {
    uint32_t a;
    asm("{ .reg .u64 t; cvta.to.shared.u64 t, %1; cvt.u32.u64 %0, t; }" : "=r"(a) : "l"(p));
    return a;
}
__device__ __forceinline__ void ldm_x4(uint32_t* r, uint32_t addr) {
    asm volatile("ldmatrix.sync.aligned.m8n8.x4.shared.b16 {%0,%1,%2,%3}, [%4];"
                 : "=r"(r[0]), "=r"(r[1]), "=r"(r[2]), "=r"(r[3]) : "r"(addr));
}
__device__ __forceinline__ void ldm_x4_trans(uint32_t* r, uint32_t addr) {
    asm volatile("ldmatrix.sync.aligned.m8n8.x4.trans.shared.b16 {%0,%1,%2,%3}, [%4];"
                 : "=r"(r[0]), "=r"(r[1]), "=r"(r[2]), "=r"(r[3]) : "r"(addr));
}
__device__ __forceinline__ void mma16816(float* c, const uint32_t* a, uint32_t b0, uint32_t b1) {
    asm volatile(
        "mma.sync.aligned.m16n8k16.row.col.f32.f16.f16.f32 "
        "{%0,%1,%2,%3}, {%4,%5,%6,%7}, {%8,%9}, {%0,%1,%2,%3};"
        : "+f"(c[0]), "+f"(c[1]), "+f"(c[2]), "+f"(c[3])
        : "r"(a[0]), "r"(a[1]), "r"(a[2]), "r"(a[3]), "r"(b0), "r"(b1));
}

// ---------------- fp32 -> (hi, lo) fp16 split conversion --------------------------
__global__ void cvt_kernel(const float* __restrict__ src, int which, int n) {
    int i = blockIdx.x * blockDim.x + threadIdx.x;
    if (i >= n) return;
    __half* hi = (which == 0) ? g_xh : (which <= 3) ? g_Wh + (size_t)(which - 1) * D * D : g_Woh;
    __half* lo = (which == 0) ? g_xl : (which <= 3) ? g_Wl + (size_t)(which - 1) * D * D : g_Wol;
    float v = src[i];
    __half h = __float2half(v);
    hi[i] = h;
    lo[i] = __float2half(v - __half2float(h));
}

// ===== QKV split-fp16 tensor GEMM: C = x @ W_z, output heads layout + hi/lo =======
__global__ void __launch_bounds__(256) qkv_tc() {
    extern __shared__ __align__(16) char sm[];
    __half* Ah = (__half*)sm;                 // [128][72]
    __half* Alo = (__half*)(sm + 18432);
    __half* Bh = (__half*)(sm + 36864);       // [64][136]
    __half* Bl = (__half*)(sm + 54272);

    int tid = threadIdx.x, lane = tid & 31, wid = tid >> 5;
    int wm = wid >> 1, wn = wid & 1;
    int row0 = blockIdx.y * 128, col0 = blockIdx.x * 128;
    int which = blockIdx.z;
    const __half* Whp = g_Wh + (size_t)which * D * D;
    const __half* Wlp = g_Wl + (size_t)which * D * D;

    float acc[2][8][4];
#pragma unroll
    for (int i = 0; i < 2; i++)
#pragma unroll
        for (int j = 0; j < 8; j++)
#pragma unroll
            for (int l = 0; l < 4; l++) acc[i][j][l] = 0.f;

    uint32_t ah_b = smem_u32(Ah), al_b = smem_u32(Alo);
    uint32_t bh_b = smem_u32(Bh), bl_b = smem_u32(Bl);
    int lm = lane & 15, lh = lane >> 4;

    for (int k0 = 0; k0 < D; k0 += 64) {
#pragma unroll
        for (int e = 0; e < 4; e++) {
            int idx = tid + 256 * e;           // 0..1023
            int m = idx >> 3, c8 = idx & 7;
            *(uint4*)&Ah[m * 72 + c8 * 8]  = *(const uint4*)&g_xh[(size_t)(row0 + m) * D + k0 + c8 * 8];
            *(uint4*)&Alo[m * 72 + c8 * 8] = *(const uint4*)&g_xl[(size_t)(row0 + m) * D + k0 + c8 * 8];
            int kb = idx >> 4, c16 = idx & 15;
            *(uint4*)&Bh[kb * 136 + c16 * 8] = *(const uint4*)&Whp[(size_t)(k0 + kb) * D + col0 + c16 * 8];
            *(uint4*)&Bl[kb * 136 + c16 * 8] = *(const uint4*)&Wlp[(size_t)(k0 + kb) * D + col0 + c16 * 8];
        }
        __syncthreads();
#pragma unroll
        for (int kk = 0; kk < 64; kk += 16) {
            uint32_t a_h[2][4], a_l[2][4];
#pragma unroll
            for (int mt = 0; mt < 2; mt++) {
                ldm_x4(a_h[mt], ah_b + ((wm * 32 + mt * 16 + lm) * 72 + kk + lh * 8) * 2);
                ldm_x4(a_l[mt], al_b + ((wm * 32 + mt * 16 + lm) * 72 + kk + lh * 8) * 2);
            }
#pragma unroll
            for (int ng = 0; ng < 4; ng++) {
                uint32_t b_h[4], b_l[4];
                ldm_x4_trans(b_h, bh_b + ((kk + lm) * 136 + wn * 64 + ng * 16 + lh * 8) * 2);
                ldm_x4_trans(b_l, bl_b + ((kk + lm) * 136 + wn * 64 + ng * 16 + lh * 8) * 2);
#pragma unroll
                for (int mt = 0; mt < 2; mt++) {
                    mma16816(acc[mt][ng * 2 + 0], a_h[mt], b_h[0], b_h[1]);
                    mma16816(acc[mt][ng * 2 + 0], a_h[mt], b_l[0], b_l[1]);
                    mma16816(acc[mt][ng * 2 + 0], a_l[mt], b_h[0], b_h[1]);
                    mma16816(acc[mt][ng * 2 + 1], a_h[mt], b_h[2], b_h[3]);
                    mma16816(acc[mt][ng * 2 + 1], a_h[mt], b_l[2], b_l[3]);
                    mma16816(acc[mt][ng * 2 + 1], a_l[mt], b_h[2], b_h[3]);
                }
            }
        }
        __syncthreads();
    }

    float* outF = (which == 0) ? g_q : (which == 1) ? g_k : g_v;
    __half* oh = (which == 0) ? g_qhh : g_khh;
    __half* ol = (which == 0) ? g_qll : g_kll;
#pragma unroll
    for (int mt = 0; mt < 2; mt++) {
        int r0 = row0 + wm * 32 + mt * 16 + (lane >> 2);
#pragma unroll
        for (int nt = 0; nt < 8; nt++) {
            int c = col0 + wn * 64 + nt * 8 + (lane & 3) * 2;
            int hh = c >> 6, dh = c & 63;
#pragma unroll
            for (int rr = 0; rr < 2; rr++) {
                int s = r0 + rr * 8;
                float v0 = acc[mt][nt][rr * 2 + 0], v1 = acc[mt][nt][rr * 2 + 1];
                size_t gi = ((size_t)hh * S + s) * DH + dh;
                *(float2*)&outF[gi] = make_float2(v0, v1);
                if (which < 2) {
                    __half h0 = __float2half(v0), h1 = __float2half(v1);
                    *(__half2*)&oh[gi] = __halves2half2(h0, h1);
                    *(__half2*)&ol[gi] = __halves2half2(
                        __float2half(v0 - __half2float(h0)),
                        __float2half(v1 - __half2float(h1)));
                }
            }
        }
    }
}

// ---------------- row norms of q and k ----------------
__global__ void norms_kernel() {
    int gw = (blockIdx.x * blockDim.x + threadIdx.x) >> 5;
    int lane = threadIdx.x & 31;
    if (gw >= 2 * H * S) return;
    const float* src = (gw < H * S) ? g_q : g_k;
    float* dst = (gw < H * S) ? g_qn : g_kn;
    int row = (gw < H * S) ? gw : gw - H * S;
    const float* p = src + (size_t)row * DH;
    float a = p[lane], b = p[lane + 32];
    float sum = a * a + b * b;
#pragma unroll
    for (int o = 16; o > 0; o >>= 1) sum += __shfl_xor_sync(0xffffffffu, sum, o);
    if (lane == 0) dst[row] = sum;
}

// ---------------- transpose k hi/lo: [h][s][dh] -> [h][dh][s] ----------------------
__global__ void transpose_k() {
    __shared__ __half t0[32][33];
    __shared__ __half t1[32][33];
    int h = blockIdx.z;
    int s0 = blockIdx.x * 32, d0 = blockIdx.y * 32;
    int tx = threadIdx.x, ty = threadIdx.y;   // 32 x 8
#pragma unroll
    for (int i = 0; i < 32; i += 8) {
        t0[ty + i][tx] = g_khh[((size_t)h * S + s0 + ty + i) * DH + d0 + tx];
        t1[ty + i][tx] = g_kll[((size_t)h * S + s0 + ty + i) * DH + d0 + tx];
    }
    __syncthreads();
#pragma unroll
    for (int i = 0; i < 32; i += 8) {
        g_kTh[((size_t)h * DH + d0 + ty + i) * S + s0 + tx] = t0[tx][ty + i];
        g_kTl[((size_t)h * DH + d0 + ty + i) * S + s0 + tx] = t1[tx][ty + i];
    }
}

// ===== fused kmat: phase1 row-min (hi-only), phase2 normalized exp -> fp16 Kh =====
__global__ void __launch_bounds__(256) kmat_tc(const float* __restrict__ bw_p) {
    extern __shared__ __align__(16) char sm[];
    __half* Qh = (__half*)sm;                 // [128][72]
    __half* Ql = (__half*)(sm + 18432);
    __half* Bh = (__half*)(sm + 36864);       // kT tile [64][136]
    __half* Bl = (__half*)(sm + 54272);
    float* qn_s = (float*)(sm + 71680);
    float* kn_s = (float*)(sm + 72192);
    unsigned* minv = (unsigned*)(sm + 72704);

    int tid = threadIdx.x, lane = tid & 31, wid = tid >> 5;
    int h = blockIdx.y, i0 = blockIdx.x * 128;
    float bw = softplusf(bw_p[0]) + 1e-6f;
    float inv = 1.0f / (2.0f * bw * bw);

#pragma unroll
    for (int e = 0; e < 4; e++) {
        int idx = tid + 256 * e;
        int m = idx >> 3, c8 = idx & 7;
        *(uint4*)&Qh[m * 72 + c8 * 8] = *(const uint4*)&g_qhh[((size_t)h * S + i0 + m) * DH + c8 * 8];
        *(uint4*)&Ql[m * 72 + c8 * 8] = *(const uint4*)&g_qll[((size_t)h * S + i0 + m) * DH + c8 * 8];
    }
    if (tid < 128) {
        qn_s[tid] = g_qn[h * S + i0 + tid];
        minv[tid] = 0x7F800000u;
    }
    __syncthreads();

    uint32_t qh_b = smem_u32(Qh), ql_b = smem_u32(Ql);
    uint32_t bh_b = smem_u32(Bh), bl_b = smem_u32(Bl);
    int lm = lane & 15, lh = lane >> 4;

    const __half* kThp = g_kTh + (size_t)h * DH * S;
    const __half* kTlp = g_kTl + (size_t)h * DH * S;

    float rmin[16];
#pragma unroll
    for (int i = 0; i < 16; i++) rmin[i] = 3.4e38f;

    // ---------------- phase 1: hi-only dist, track row mins -----------------------
    for (int j0 = 0; j0 < S; j0 += 128) {
#pragma unroll
        for (int e = 0; e < 4; e++) {
            int idx = tid + 256 * e;
            int kb = idx >> 4, c16 = idx & 15;
            *(uint4*)&Bh[kb * 136 + c16 * 8] = *(const uint4*)&kThp[(size_t)kb * S + j0 + c16 * 8];
        }
        if (tid < 128) kn_s[tid] = g_kn[h * S + j0 + tid];
        __syncthreads();

        uint32_t bf[4][4];
#pragma unroll
        for (int k4 = 0; k4 < 4; k4++)
            ldm_x4_trans(bf[k4], bh_b + ((k4 * 16 + lm) * 136 + wid * 16 + lh * 8) * 2);

#pragma unroll
        for (int mt = 0; mt < 8; mt++) {
            float a0[4] = {0.f, 0.f, 0.f, 0.f}, a1[4] = {0.f, 0.f, 0.f, 0.f};
#pragma unroll
            for (int k4 = 0; k4 < 4; k4++) {
                uint32_t a[4];
                ldm_x4(a, qh_b + ((mt * 16 + lm) * 72 + k4 * 16 + lh * 8) * 2);
                mma16816(a0, a, bf[k4][0], bf[k4][1]);
                mma16816(a1, a, bf[k4][2], bf[k4][3]);
            }
            int r = mt * 16 + (lane >> 2);
            float qn0 = qn_s[r], qn1 = qn_s[r + 8];
            int cb = wid * 16 + (lane & 3) * 2;
            float kn0 = kn_s[cb], kn1 = kn_s[cb + 1], kn8 = kn_s[cb + 8], kn9 = kn_s[cb + 9];
            float d0 = fminf(fminf(qn0 + kn0 - 2.f * a0[0], qn0 + kn1 - 2.f * a0[1]),
                             fminf(qn0 + kn8 - 2.f * a1[0], qn0 + kn9 - 2.f * a1[1]));
            float d1 = fminf(fminf(qn1 + kn0 - 2.f * a0[2], qn1 + kn1 - 2.f * a0[3]),
                             fminf(qn1 + kn8 - 2.f * a1[2], qn1 + kn9 - 2.f * a1[3]));
            rmin[mt * 2] = fminf(rmin[mt * 2], d0);
            rmin[mt * 2 + 1] = fminf(rmin[mt * 2 + 1], d1);
        }
        __syncthreads();
    }
#pragma unroll
    for (int i = 0; i < 16; i++) {
        rmin[i] = fminf(rmin[i], __shfl_xor_sync(0xffffffffu, rmin[i], 1));
        rmin[i] = fminf(rmin[i], __shfl_xor_sync(0xffffffffu, rmin[i], 2));
    }
    if ((lane & 3) == 0) {
#pragma unroll
        for (int mt = 0; mt < 8; mt++) {
            atomicMin(&minv[mt * 16 + (lane >> 2)], __float_as_uint(fmaxf(rmin[mt * 2], 0.f)));
            atomicMin(&minv[mt * 16 + (lane >> 2) + 8], __float_as_uint(fmaxf(rmin[mt * 2 + 1], 0.f)));
        }
    }
    __syncthreads();
    if (tid < 128)
        g_scale[h * S + i0 + tid] = __expf(-__uint_as_float(minv[tid]) * inv);

    // ---------------- phase 2: split dist, exp -> Kh fp16 -------------------------
    for (int j0 = 0; j0 < S; j0 += 128) {
#pragma unroll
        for (int e = 0; e < 4; e++) {
            int idx = tid + 256 * e;
            int kb = idx >> 4, c16 = idx & 15;
            *(uint4*)&Bh[kb * 136 + c16 * 8] = *(const uint4*)&kThp[(size_t)kb * S + j0 + c16 * 8];
            *(uint4*)&Bl[kb * 136 + c16 * 8] = *(const uint4*)&kTlp[(size_t)kb * S + j0 + c16 * 8];
        }
        if (tid < 128) kn_s[tid] = g_kn[h * S + j0 + tid];
        __syncthreads();

        uint32_t bfh[4][4], bfl[4][4];
#pragma unroll
        for (int k4 = 0; k4 < 4; k4++) {
            ldm_x4_trans(bfh[k4], bh_b + ((k4 * 16 + lm) * 136 + wid * 16 + lh * 8) * 2);
            ldm_x4_trans(bfl[k4], bl_b + ((k4 * 16 + lm) * 136 + wid * 16 + lh * 8) * 2);
        }

#pragma unroll
        for (int mt = 0; mt < 8; mt++) {
            float a0[4] = {0.f, 0.f, 0.f, 0.f}, a1[4] = {0.f, 0.f, 0.f, 0.f};
#pragma unroll
            for (int k4 = 0; k4 < 4; k4++) {
                uint32_t ah[4], al[4];
                ldm_x4(ah, qh_b + ((mt * 16 + lm) * 72 + k4 * 16 + lh * 8) * 2);
                ldm_x4(al, ql_b + ((mt * 16 + lm) * 72 + k4 * 16 + lh * 8) * 2);
                mma16816(a0, ah, bfh[k4][0], bfh[k4][1]);
                mma16816(a0, ah, bfl[k4][0], bfl[k4][1]);
                mma16816(a0, al, bfh[k4][0], bfh[k4][1]);
                mma16816(a1, ah, bfh[k4][2], bfh[k4][3]);
                mma16816(a1, ah, bfl[k4][2], bfl[k4][3]);
                mma16816(a1, al, bfh[k4][2], bfh[k4][3]);
            }
            int r = mt * 16 + (lane >> 2);
            float qn0 = qn_s[r], qn1 = qn_s[r + 8];
            float dm0 = __uint_as_float(minv[r]), dm1 = __uint_as_float(minv[r + 8]);
            int cb = wid * 16 + (lane & 3) * 2;
            float kn0 = kn_s[cb], kn1 = kn_s[cb + 1], kn8 = kn_s[cb + 8], kn9 = kn_s[cb + 9];
            float e00 = __expf((dm0 - fmaxf(qn0 + kn0 - 2.f * a0[0], 0.f)) * inv);
            float e01 = __expf((dm0 - fmaxf(qn0 + kn1 - 2.f * a0[1], 0.f)) * inv);
            float e10 = __expf((dm1 - fmaxf(qn1 + kn0 - 2.f * a0[2], 0.f)) * inv);
            float e11 = __expf((dm1 - fmaxf(qn1 + kn1 - 2.f * a0[3], 0.f)) * inv);
            float f00 = __expf((dm0 - fmaxf(qn0 + kn8 - 2.f * a1[0], 0.f)) * inv);
            float f01 = __expf((dm0 - fmaxf(qn0 + kn9 - 2.f * a1[1], 0.f)) * inv);
            float f10 = __expf((dm1 - fmaxf(qn1 + kn8 - 2.f * a1[2], 0.f)) * inv);
            float f11 = __expf((dm1 - fmaxf(qn1 + kn9 - 2.f * a1[3], 0.f)) * inv);
            __half* Kp0 = &g_Kh[((size_t)(h * S + i0 + r)) * S + j0 + cb];
            __half* Kp1 = Kp0 + (size_t)8 * S;
            *(__half2*)Kp0 = __halves2half2(__float2half(e00), __float2half(e01));
            *(__half2*)(Kp0 + 8) = __halves2half2(__float2half(f00), __float2half(f01));
            *(__half2*)Kp1 = __halves2half2(__float2half(e10), __float2half(e11));
            *(__half2*)(Kp1 + 8) = __halves2half2(__float2half(f10), __float2half(f11));
        }
        __syncthreads();
    }
}

// ---------------- diag_p from exact fp32 (q-k)^2 ----------------------------------
__global__ void diag_kernel(const float* __restrict__ diag_scale,
                            const float* __restrict__ reg_p,
                            const float* __restrict__ bw_p) {
    int gw = (blockIdx.x * blockDim.x + threadIdx.x) >> 5;
    int lane = threadIdx.x & 31;
    if (gw >= H * S) return;
    const float* qp = g_q + (size_t)gw * DH;
    const float* kp = g_k + (size_t)gw * DH;
    float d0 = qp[lane] - kp[lane], d1 = qp[lane + 32] - kp[lane + 32];
    float sum = d0 * d0 + d1 * d1;
#pragma unroll
    for (int o = 16; o > 0; o >>= 1) sum += __shfl_xor_sync(0xffffffffu, sum, o);
    if (lane == 0) {
        float bw = softplusf(bw_p[0]) + 1e-6f;
        float inv = 1.0f / (2.0f * bw * bw);
        float kd = __expf(-sum * inv);
        g_diagp[gw] = softplusf(kd) * diag_scale[gw / S] + reg_p[0];
    }
}

// ---------------- U[h,s,r] = sum_rp pos[s,rp] * proj[h,rp,r] ----------------------
__global__ void u_kernel(const float* __restrict__ pos, const float* __restrict__ proj) {
    __shared__ float pr[RANK][RANK];
    int h = blockIdx.y;
    int tid = threadIdx.x;
    pr[tid >> 4][tid & 15] = proj[h * RANK * RANK + tid];
    __syncthreads();
    int s = blockIdx.x * 256 + tid;
    float pe[RANK];
#pragma unroll
    for (int r = 0; r < RANK; r++) pe[r] = pos[(size_t)s * RANK + r];
#pragma unroll
    for (int r = 0; r < RANK; r++) {
        float acc = 0.f;
#pragma unroll
        for (int rp = 0; rp < RANK; rp++) acc += pe[rp] * pr[rp][r];
        g_U[((size_t)h * S + s) * RANK + r] = acc;
    }
}

// ---------------- alpha = 0; r = v -------------------------------------------------
__global__ void init_kernel() {
    int i = blockIdx.x * blockDim.x + threadIdx.x;
    if (i < H * S * DH) {
        g_alpha[i] = 0.0f;
        g_r[i] = g_v[i];
    }
}

// == HMMA K@alpha: mode0: r=v-scale*K'a-lam*a; mode1: store NORMALIZED K'a hi/lo ===
__global__ void __launch_bounds__(256) kapply_mma(int mode, const float* __restrict__ lam_p) {
    __shared__ __half Ks[128][72];
    __shared__ __half Al[64][72];

    int tid = threadIdx.x, wid = tid >> 5, lane = tid & 31;
    int h = blockIdx.y;
    int s0 = blockIdx.x * 128;

    const __half* Kb = g_Kh + ((size_t)h * S + s0) * S;
    const __half* Ab = g_alphaH + (size_t)h * S * DH;

    float acc[8][4];
#pragma unroll
    for (int i = 0; i < 8; i++)
#pragma unroll
        for (int j = 0; j < 4; j++) acc[i][j] = 0.f;

    uint32_t ks_base = smem_u32(&Ks[0][0]);
    uint32_t al_base = smem_u32(&Al[0][0]);
    int lm = lane & 15, lh = lane >> 4;

    for (int t0 = 0; t0 < S; t0 += 64) {
#pragma unroll
        for (int e = 0; e < 4; e++) {
            int idx = tid + 256 * e;
            int m = idx >> 3, c8 = idx & 7;
            *(uint4*)&Ks[m][c8 * 8] = *(const uint4*)(Kb + (size_t)m * S + t0 + c8 * 8);
        }
#pragma unroll
        for (int e = 0; e < 2; e++) {
            int idx = tid + 256 * e;
            int t = idx >> 3, c8 = idx & 7;
            *(uint4*)&Al[t][c8 * 8] = *(const uint4*)(Ab + (size_t)(t0 + t) * DH + c8 * 8);
        }
        __syncthreads();

#pragma unroll
        for (int kk = 0; kk < 64; kk += 16) {
            uint32_t a[4];
            ldm_x4(a, ks_base + ((wid * 16 + lm) * 72 + kk + lh * 8) * 2);
#pragma unroll
            for (int nt = 0; nt < 4; nt++) {
                uint32_t b[4];
                ldm_x4_trans(b, al_base + ((kk + lm) * 72 + nt * 16 + lh * 8) * 2);
                mma16816(acc[nt * 2 + 0], a, b[0], b[1]);
                mma16816(acc[nt * 2 + 1], a, b[2], b[3]);
            }
        }
        __syncthreads();
    }

    float lam = 0.f;
    if (mode == 0) lam = softplusf(lam_p[0]);
    int rbase = s0 + wid * 16 + (lane >> 2);
    float sc0 = g_scale[h * S + rbase];
    float sc1 = g_scale[h * S + rbase + 8];
#pragma unroll
    for (int nt = 0; nt < 8; nt++) {
        int col = nt * 8 + (lane & 3) * 2;
        size_t g0 = ((size_t)h * S + rbase) * DH + col;
        size_t g1 = g0 + 8 * DH;
        if (mode == 0) {
            float2 v0 = *(const float2*)&g_v[g0];
            float2 v1 = *(const float2*)&g_v[g1];
            float2 a0 = *(const float2*)&g_alpha[g0];
            float2 a1 = *(const float2*)&g_alpha[g1];
            *(float2*)&g_r[g0] = make_float2(v0.x - sc0 * acc[nt][0] - lam * a0.x,
                                             v0.y - sc0 * acc[nt][1] - lam * a0.y);
            *(float2*)&g_r[g1] = make_float2(v1.x - sc1 * acc[nt][2] - lam * a1.x,
                                             v1.y - sc1 * acc[nt][3] - lam * a1.y);
        } else {
            // store NORMALIZED ctx (no row scale) — O(1) values, fp16-safe
            float c00 = acc[nt][0], c01 = acc[nt][1];
            float c10 = acc[nt][2], c11 = acc[nt][3];
            __half h00 = __float2half(c00), h01 = __float2half(c01);
            __half h10 = __float2half(c10), h11 = __float2half(c11);
            *(__half2*)&g_ctxH[g0] = __halves2half2(h00, h01);
            *(__half2*)&g_ctxH[g1] = __halves2half2(h10, h11);
            *(__half2*)&g_ctxL[g0] = __halves2half2(__float2half(c00 - __half2float(h00)),
                                                    __float2half(c01 - __half2float(h01)));
            *(__half2*)&g_ctxL[g1] = __halves2half2(__float2half(c10 - __half2float(h10)),
                                                    __float2half(c11 - __half2float(h11)));
        }
    }
}

// ---------------- utr_part[p,h,r,d] = sum_{s in part} U[h,s,r] * r[h,s,d] ---------
__global__ void utr_kernel() {
    int h = blockIdx.x;
    int part = blockIdx.y;
    int tid = threadIdx.x;
    int d = tid & 63, rr = tid >> 6;
    const float* Ub = g_U + (size_t)h * S * RANK;
    const float* rb = g_r + (size_t)h * S * DH;
    int s0 = part * (S / 8);
    float a0 = 0, a1 = 0, a2 = 0, a3 = 0;
    for (int s = s0; s < s0 + S / 8; s += 4) {
        a0 += Ub[(s + 0) * RANK + rr] * rb[(size_t)(s + 0) * DH + d];
        a1 += Ub[(s + 1) * RANK + rr] * rb[(size_t)(s + 1) * DH + d];
        a2 += Ub[(s + 2) * RANK + rr] * rb[(size_t)(s + 2) * DH + d];
        a3 += Ub[(s + 3) * RANK + rr] * rb[(size_t)(s + 3) * DH + d];
    }
    g_utr_part[((part * H + h) * RANK + rr) * DH + d] = (a0 + a1) + (a2 + a3);
}

// ---------------- alpha += r*diag_p + U @ utr; emit fp16 mirror -------------------
__global__ void update_kernel() {
    __shared__ float ut[RANK][DH];
    __shared__ float Us[16][RANK];
    int h = blockIdx.y;
    int tid = threadIdx.x;
    {
        float sum = 0.f;
#pragma unroll
        for (int p = 0; p < 8; p++) sum += g_utr_part[(p * H + h) * RANK * DH + tid];
        ut[tid >> 6][tid & 63] = sum;
    }
    int s0 = blockIdx.x * 16;
    if (tid < 16 * RANK)
        Us[tid >> 4][tid & 15] = g_U[((size_t)h * S + s0 + (tid >> 4)) * RANK + (tid & 15)];
    __syncthreads();

    int sl = tid >> 6;
    int d = tid & 63;
    int s = s0 + sl;
    size_t idx = ((size_t)h * S + s) * DH + d;
    float acc = 0.f;
#pragma unroll
    for (int r2 = 0; r2 < RANK; r2++) acc += Us[sl][r2] * ut[r2][d];
    float na = g_alpha[idx] + g_r[idx] * g_diagp[h * S + s] + acc;
    g_alpha[idx] = na;
    g_alphaH[idx] = __float2half(na);
}

// == output GEMM: out = (scale ⊙ ctxN)_flat @ Wo; per-head-block scale folding =====
__global__ void __launch_bounds__(256) wo_tc(float* __restrict__ out) {
    extern __shared__ __align__(16) char sm[];
    __half* Ah = (__half*)sm;                 // [128][72]
    __half* Alo = (__half*)(sm + 18432);
    __half* Bh = (__half*)(sm + 36864);       // [64][136]
    __half* Bl = (__half*)(sm + 54272);
    float* scs = (float*)(sm + 71680);        // 128 row scales for current head

    int tid = threadIdx.x, lane = tid & 31, wid = tid >> 5;
    int wm = wid >> 1, wn = wid & 1;
    int row0 = blockIdx.y * 128, col0 = blockIdx.x * 128;

    float acc[2][8][4];
#pragma unroll
    for (int i = 0; i < 2; i++)
#pragma unroll
        for (int j = 0; j < 8; j++)
#pragma unroll
            for (int l = 0; l < 4; l++) acc[i][j][l] = 0.f;

    uint32_t ah_b = smem_u32(Ah), al_b = smem_u32(Alo);
    uint32_t bh_b = smem_u32(Bh), bl_b = smem_u32(Bl);
    int lm = lane & 15, lh = lane >> 4;

    for (int ck = 0; ck < 16; ck++) {          // head / k-block
        int k0 = ck * 64;
#pragma unroll
        for (int e = 0; e < 4; e++) {
            int idx = tid + 256 * e;
            int m = idx >> 3, c8 = idx & 7;
            *(uint4*)&Ah[m * 72 + c8 * 8]  = *(const uint4*)&g_ctxH[((size_t)ck * S + row0 + m) * DH + c8 * 8];
            *(uint4*)&Alo[m * 72 + c8 * 8] = *(const uint4*)&g_ctxL[((size_t)ck * S + row0 + m) * DH + c8 * 8];
            int kb = idx >> 4, c16 = idx & 15;
            *(uint4*)&Bh[kb * 136 + c16 * 8] = *(const uint4*)&g_Woh[(size_t)(k0 + kb) * D + col0 + c16 * 8];
            *(uint4*)&Bl[kb * 136 + c16 * 8] = *(const uint4*)&g_Wol[(size_t)(k0 + kb) * D + col0 + c16 * 8];
        }
        if (tid < 128) scs[tid] = g_scale[ck * S + row0 + tid];
        __syncthreads();

        float accp[2][8][4];
#pragma unroll
        for (int i = 0; i < 2; i++)
#pragma unroll
            for (int j = 0; j < 8; j++)
#pragma unroll
                for (int l = 0; l < 4; l++) accp[i][j][l] = 0.f;

#pragma unroll
        for (int kk = 0; kk < 64; kk += 16) {
            uint32_t a_h[2][4], a_l[2][4];
#pragma unroll
            for (int mt = 0; mt < 2; mt++) {
                ldm_x4(a_h[mt], ah_b + ((wm * 32 + mt * 16 + lm) * 72 + kk + lh * 8) * 2);
                ldm_x4(a_l[mt], al_b + ((wm * 32 + mt * 16 + lm) * 72 + kk + lh * 8) * 2);
            }
#pragma unroll
            for (int ng = 0; ng < 4; ng++) {
                uint32_t b_h[4], b_l[4];
                ldm_x4_trans(b_h, bh_b + ((kk + lm) * 136 + wn * 64 + ng * 16 + lh * 8) * 2);
                ldm_x4_trans(b_l, bl_b + ((kk + lm) * 136 + wn * 64 + ng * 16 + lh * 8) * 2);
#pragma unroll
                for (int mt = 0; mt < 2; mt++) {
                    mma16816(accp[mt][ng * 2 + 0], a_h[mt], b_h[0], b_h[1]);
                    mma16816(accp[mt][ng * 2 + 0], a_h[mt], b_l[0], b_l[1]);
                    mma16816(accp[mt][ng * 2 + 0], a_l[mt], b_h[0], b_h[1]);
                    mma16816(accp[mt][ng * 2 + 1], a_h[mt], b_h[2], b_h[3]);
                    mma16816(accp[mt][ng * 2 + 1], a_h[mt], b_l[2], b_l[3]);
                    mma16816(accp[mt][ng * 2 + 1], a_l[mt], b_h[2], b_h[3]);
                }
            }
        }

        // fold with per-row scale of this head block
#pragma unroll
        for (int mt = 0; mt < 2; mt++) {
            int rl = wm * 32 + mt * 16 + (lane >> 2);
            float sc0 = scs[rl], sc1 = scs[rl + 8];
#pragma unroll
            for (int nt = 0; nt < 8; nt++) {
                acc[mt][nt][0] += sc0 * accp[mt][nt][0];
                acc[mt][nt][1] += sc0 * accp[mt][nt][1];
                acc[mt][nt][2] += sc1 * accp[mt][nt][2];
                acc[mt][nt][3] += sc1 * accp[mt][nt][3];
            }
        }
        __syncthreads();
    }

#pragma unroll
    for (int mt = 0; mt < 2; mt++) {
        int r0 = row0 + wm * 32 + mt * 16 + (lane >> 2);
#pragma unroll
        for (int nt = 0; nt < 8; nt++) {
            int c = col0 + wn * 64 + nt * 8 + (lane & 3) * 2;
#pragma unroll
            for (int rr = 0; rr < 2; rr++) {
                int s = r0 + rr * 8;
                *(float2*)&out[(size_t)s * D + c] =
                    make_float2(acc[mt][nt][rr * 2 + 0], acc[mt][nt][rr * 2 + 1]);
            }
        }
    }
}

// ---------------- launch ----------------------------------------------------------
extern "C" void kernel_launch(void* const* d_in, const int* in_sizes, int n_in,
                              void* d_out, int out_size) {
    const float* x          = (const float*)d_in[0];
    const float* Wq         = (const float*)d_in[1];
    const float* Wk         = (const float*)d_in[2];
    const float* Wv         = (const float*)d_in[3];
    const float* Wo         = (const float*)d_in[4];
    const float* bandwidth  = (const float*)d_in[5];
    const float* diag_scale = (const float*)d_in[6];
    const float* pos        = (const float*)d_in[7];
    const float* proj       = (const float*)d_in[8];
    const float* reg        = (const float*)d_in[9];
    const float* lam        = (const float*)d_in[10];
    float* out = (float*)d_out;

    static bool attr_done = false;
    if (!attr_done) {
        cudaFuncSetAttribute(qkv_tc, cudaFuncAttributeMaxDynamicSharedMemorySize, 71680);
        cudaFuncSetAttribute(wo_tc, cudaFuncAttributeMaxDynamicSharedMemorySize, 72192);
        cudaFuncSetAttribute(kmat_tc, cudaFuncAttributeMaxDynamicSharedMemorySize, 73216);
        attr_done = true;
    }

    cvt_kernel<<<(S * D + 255) / 256, 256>>>(x, 0, S * D);
    cvt_kernel<<<(D * D + 255) / 256, 256>>>(Wq, 1, D * D);
    cvt_kernel<<<(D * D + 255) / 256, 256>>>(Wk, 2, D * D);
    cvt_kernel<<<(D * D + 255) / 256, 256>>>(Wv, 3, D * D);
    cvt_kernel<<<(D * D + 255) / 256, 256>>>(Wo, 4, D * D);

    qkv_tc<<<dim3(D / 128, S / 128, 3), 256, 71680>>>();
    norms_kernel<<<(2 * H * S * 32 + 255) / 256, 256>>>();
    transpose_k<<<dim3(S / 32, DH / 32, H), dim3(32, 8)>>>();
    kmat_tc<<<dim3(S / 128, H), 256, 73216>>>(bandwidth);
    diag_kernel<<<(H * S * 32 + 255) / 256, 256>>>(diag_scale, reg, bandwidth);
    u_kernel<<<dim3(S / 256, H), 256>>>(pos, proj);

    // Richardson iteration 1: alpha = 0 => r = v
    init_kernel<<<(H * S * DH + 255) / 256, 256>>>();
    utr_kernel<<<dim3(H, 8), 1024>>>();
    update_kernel<<<dim3(S / 16, H), 1024>>>();

    for (int it = 1; it < 5; it++) {
        kapply_mma<<<dim3(S / 128, H), 256>>>(0, lam);
        utr_kernel<<<dim3(H, 8), 1024>>>();
        update_kernel<<<dim3(S / 16, H), 1024>>>();
    }

    kapply_mma<<<dim3(S / 128, H), 256>>>(1, lam);
    wo_tc<<<dim3(D / 128, S / 128), 256, 72192>>>(out);
}

// round 7
// speedup vs baseline: 3.5429x; 1.1101x over previous
#include <cuda_runtime.h>
#include <cuda_fp16.h>
#include <math.h>
#include <cstdint>

#define H 16
#define S 2048
#define D 1024
#define DH 64
#define RANK 16

// ---------------- scratch (device globals; no allocation allowed) ----------------
__device__ float g_q[H * S * DH];
__device__ float g_k[H * S * DH];
__device__ float g_v[H * S * DH];
__device__ float g_alpha[H * S * DH];
__device__ __half g_alphaH[H * S * DH];
__device__ float g_r[H * S * DH];
__device__ __half g_ctxH[H * S * DH];   // normalized ctx = K'@alpha (hi)
__device__ __half g_ctxL[H * S * DH];   // normalized ctx (lo)
__device__ __half g_Kh[(size_t)H * S * S];       // 128 MB fp16 row-normalized kernel
__device__ float g_scale[H * S];                 // per-row scale exp(-dmin*inv)
__device__ float g_qn[H * S];
__device__ float g_kn[H * S];
__device__ float g_diagp[H * S];
__device__ float g_U[H * S * RANK];
__device__ float g_utr_part[8 * H * RANK * DH];

// split fp16 operands
__device__ __half g_xh[S * D],  g_xl[S * D];
__device__ __half g_Wh[3 * D * D], g_Wl[3 * D * D];   // Wq, Wk, Wv
__device__ __half g_Woh[D * D], g_Wol[D * D];
__device__ __half g_qhh[H * S * DH], g_qll[H * S * DH];
__device__ __half g_khh[H * S * DH], g_kll[H * S * DH];
__device__ __half g_kTh[H * DH * S], g_kTl[H * DH * S];  // transposed k

__device__ __forceinline__ float softplusf(float x) {
    return (x > 20.f) ? x : log1pf(expf(x));
}

// ======================= HMMA helpers (mma.sync + ldmatrix) =======================
__device__ __forceinline__ uint32_t smem_u32(const void* p) {
    uint32_t a;
    asm("{ .reg .u64 t; cvta.to.shared.u64 t, %1; cvt.u32.u64 %0, t; }" : "=r"(a) : "l"(p));
    return a;
}
__device__ __forceinline__ void ldm_x4(uint32_t* r, uint32_t addr) {
    asm volatile("ldmatrix.sync.aligned.m8n8.x4.shared.b16 {%0,%1,%2,%3}, [%4];"
                 : "=r"(r[0]), "=r"(r[1]), "=r"(r[2]), "=r"(r[3]) : "r"(addr));
}
__device__ __forceinline__ void ldm_x4_trans(uint32_t* r, uint32_t addr) {
    asm volatile("ldmatrix.sync.aligned.m8n8.x4.trans.shared.b16 {%0,%1,%2,%3}, [%4];"
                 : "=r"(r[0]), "=r"(r[1]), "=r"(r[2]), "=r"(r[3]) : "r"(addr));
}
__device__ __forceinline__ void mma16816(float* c, const uint32_t* a, uint32_t b0, uint32_t b1) {
    asm volatile(
        "mma.sync.aligned.m16n8k16.row.col.f32.f16.f16.f32 "
        "{%0,%1,%2,%3}, {%4,%5,%6,%7}, {%8,%9}, {%0,%1,%2,%3};"
        : "+f"(c[0]), "+f"(c[1]), "+f"(c[2]), "+f"(c[3])
        : "r"(a[0]), "r"(a[1]), "r"(a[2]), "r"(a[3]), "r"(b0), "r"(b1));
}
__device__ __forceinline__ void cp_async16(uint32_t saddr, const void* gaddr) {
    asm volatile("cp.async.cg.shared.global [%0], [%1], 16;" :: "r"(saddr), "l"(gaddr) : "memory");
}

// ---------------- fp32 -> (hi, lo) fp16 split conversion (merged) -----------------
__global__ void cvt_all(const float* __restrict__ x, const float* __restrict__ wq,
                        const float* __restrict__ wk, const float* __restrict__ wv,
                        const float* __restrict__ wo) {
    int i = blockIdx.x * blockDim.x + threadIdx.x;
    const int NX = S * D, NW = D * D;
    const float* src;
    __half *hi, *lo;
    int off;
    if (i < NX)               { src = x;  hi = g_xh;           lo = g_xl;           off = i; }
    else if (i < NX + NW)     { src = wq; hi = g_Wh;           lo = g_Wl;           off = i - NX; }
    else if (i < NX + 2 * NW) { src = wk; hi = g_Wh + NW;      lo = g_Wl + NW;      off = i - NX - NW; }
    else if (i < NX + 3 * NW) { src = wv; hi = g_Wh + 2 * NW;  lo = g_Wl + 2 * NW;  off = i - NX - 2 * NW; }
    else if (i < NX + 4 * NW) { src = wo; hi = g_Woh;          lo = g_Wol;          off = i - NX - 3 * NW; }
    else return;
    float v = src[off];
    __half h = __float2half(v);
    hi[off] = h;
    lo[off] = __float2half(v - __half2float(h));
}

// ===== QKV split-fp16 tensor GEMM: C = x @ W_z, output heads layout + hi/lo =======
__global__ void __launch_bounds__(256) qkv_tc() {
    extern __shared__ __align__(16) char sm[];
    __half* Ah = (__half*)sm;                 // [128][72]
    __half* Alo = (__half*)(sm + 18432);
    __half* Bh = (__half*)(sm + 36864);       // [64][136]
    __half* Bl = (__half*)(sm + 54272);

    int tid = threadIdx.x, lane = tid & 31, wid = tid >> 5;
    int wm = wid >> 1, wn = wid & 1;
    int row0 = blockIdx.y * 128, col0 = blockIdx.x * 128;
    int which = blockIdx.z;
    const __half* Whp = g_Wh + (size_t)which * D * D;
    const __half* Wlp = g_Wl + (size_t)which * D * D;

    float acc[2][8][4];
#pragma unroll
    for (int i = 0; i < 2; i++)
#pragma unroll
        for (int j = 0; j < 8; j++)
#pragma unroll
            for (int l = 0; l < 4; l++) acc[i][j][l] = 0.f;

    uint32_t ah_b = smem_u32(Ah), al_b = smem_u32(Alo);
    uint32_t bh_b = smem_u32(Bh), bl_b = smem_u32(Bl);
    int lm = lane & 15, lh = lane >> 4;

    for (int k0 = 0; k0 < D; k0 += 64) {
#pragma unroll
        for (int e = 0; e < 4; e++) {
            int idx = tid + 256 * e;           // 0..1023
            int m = idx >> 3, c8 = idx & 7;
            *(uint4*)&Ah[m * 72 + c8 * 8]  = *(const uint4*)&g_xh[(size_t)(row0 + m) * D + k0 + c8 * 8];
            *(uint4*)&Alo[m * 72 + c8 * 8] = *(const uint4*)&g_xl[(size_t)(row0 + m) * D + k0 + c8 * 8];
            int kb = idx >> 4, c16 = idx & 15;
            *(uint4*)&Bh[kb * 136 + c16 * 8] = *(const uint4*)&Whp[(size_t)(k0 + kb) * D + col0 + c16 * 8];
            *(uint4*)&Bl[kb * 136 + c16 * 8] = *(const uint4*)&Wlp[(size_t)(k0 + kb) * D + col0 + c16 * 8];
        }
        __syncthreads();
#pragma unroll
        for (int kk = 0; kk < 64; kk += 16) {
            uint32_t a_h[2][4], a_l[2][4];
#pragma unroll
            for (int mt = 0; mt < 2; mt++) {
                ldm_x4(a_h[mt], ah_b + ((wm * 32 + mt * 16 + lm) * 72 + kk + lh * 8) * 2);
                ldm_x4(a_l[mt], al_b + ((wm * 32 + mt * 16 + lm) * 72 + kk + lh * 8) * 2);
            }
#pragma unroll
            for (int ng = 0; ng < 4; ng++) {
                uint32_t b_h[4], b_l[4];
                ldm_x4_trans(b_h, bh_b + ((kk + lm) * 136 + wn * 64 + ng * 16 + lh * 8) * 2);
                ldm_x4_trans(b_l, bl_b + ((kk + lm) * 136 + wn * 64 + ng * 16 + lh * 8) * 2);
#pragma unroll
                for (int mt = 0; mt < 2; mt++) {
                    mma16816(acc[mt][ng * 2 + 0], a_h[mt], b_h[0], b_h[1]);
                    mma16816(acc[mt][ng * 2 + 0], a_h[mt], b_l[0], b_l[1]);
                    mma16816(acc[mt][ng * 2 + 0], a_l[mt], b_h[0], b_h[1]);
                    mma16816(acc[mt][ng * 2 + 1], a_h[mt], b_h[2], b_h[3]);
                    mma16816(acc[mt][ng * 2 + 1], a_h[mt], b_l[2], b_l[3]);
                    mma16816(acc[mt][ng * 2 + 1], a_l[mt], b_h[2], b_h[3]);
                }
            }
        }
        __syncthreads();
    }

    float* outF = (which == 0) ? g_q : (which == 1) ? g_k : g_v;
    __half* oh = (which == 0) ? g_qhh : g_khh;
    __half* ol = (which == 0) ? g_qll : g_kll;
#pragma unroll
    for (int mt = 0; mt < 2; mt++) {
        int r0 = row0 + wm * 32 + mt * 16 + (lane >> 2);
#pragma unroll
        for (int nt = 0; nt < 8; nt++) {
            int c = col0 + wn * 64 + nt * 8 + (lane & 3) * 2;
            int hh = c >> 6, dh = c & 63;
#pragma unroll
            for (int rr = 0; rr < 2; rr++) {
                int s = r0 + rr * 8;
                float v0 = acc[mt][nt][rr * 2 + 0], v1 = acc[mt][nt][rr * 2 + 1];
                size_t gi = ((size_t)hh * S + s) * DH + dh;
                *(float2*)&outF[gi] = make_float2(v0, v1);
                if (which < 2) {
                    __half h0 = __float2half(v0), h1 = __float2half(v1);
                    *(__half2*)&oh[gi] = __halves2half2(h0, h1);
                    *(__half2*)&ol[gi] = __halves2half2(
                        __float2half(v0 - __half2float(h0)),
                        __float2half(v1 - __half2float(h1)));
                }
            }
        }
    }
}

// ---------------- row norms of q and k ----------------
__global__ void norms_kernel() {
    int gw = (blockIdx.x * blockDim.x + threadIdx.x) >> 5;
    int lane = threadIdx.x & 31;
    if (gw >= 2 * H * S) return;
    const float* src = (gw < H * S) ? g_q : g_k;
    float* dst = (gw < H * S) ? g_qn : g_kn;
    int row = (gw < H * S) ? gw : gw - H * S;
    const float* p = src + (size_t)row * DH;
    float a = p[lane], b = p[lane + 32];
    float sum = a * a + b * b;
#pragma unroll
    for (int o = 16; o > 0; o >>= 1) sum += __shfl_xor_sync(0xffffffffu, sum, o);
    if (lane == 0) dst[row] = sum;
}

// ---------------- transpose k hi/lo: [h][s][dh] -> [h][dh][s] ----------------------
__global__ void transpose_k() {
    __shared__ __half t0[32][33];
    __shared__ __half t1[32][33];
    int h = blockIdx.z;
    int s0 = blockIdx.x * 32, d0 = blockIdx.y * 32;
    int tx = threadIdx.x, ty = threadIdx.y;   // 32 x 8
#pragma unroll
    for (int i = 0; i < 32; i += 8) {
        t0[ty + i][tx] = g_khh[((size_t)h * S + s0 + ty + i) * DH + d0 + tx];
        t1[ty + i][tx] = g_kll[((size_t)h * S + s0 + ty + i) * DH + d0 + tx];
    }
    __syncthreads();
#pragma unroll
    for (int i = 0; i < 32; i += 8) {
        g_kTh[((size_t)h * DH + d0 + ty + i) * S + s0 + tx] = t0[tx][ty + i];
        g_kTl[((size_t)h * DH + d0 + ty + i) * S + s0 + tx] = t1[tx][ty + i];
    }
}

// ===== fused kmat: phase1 row-min (hi-only), phase2 normalized exp -> fp16 Kh =====
__global__ void __launch_bounds__(256) kmat_tc(const float* __restrict__ bw_p) {
    extern __shared__ __align__(16) char sm[];
    __half* Qh = (__half*)sm;                 // [128][72]
    __half* Ql = (__half*)(sm + 18432);
    __half* Bh = (__half*)(sm + 36864);       // kT tile [64][136]
    __half* Bl = (__half*)(sm + 54272);
    float* qn_s = (float*)(sm + 71680);
    float* kn_s = (float*)(sm + 72192);
    unsigned* minv = (unsigned*)(sm + 72704);

    int tid = threadIdx.x, lane = tid & 31, wid = tid >> 5;
    int h = blockIdx.y, i0 = blockIdx.x * 128;
    float bw = softplusf(bw_p[0]) + 1e-6f;
    float inv = 1.0f / (2.0f * bw * bw);

#pragma unroll
    for (int e = 0; e < 4; e++) {
        int idx = tid + 256 * e;
        int m = idx >> 3, c8 = idx & 7;
        *(uint4*)&Qh[m * 72 + c8 * 8] = *(const uint4*)&g_qhh[((size_t)h * S + i0 + m) * DH + c8 * 8];
        *(uint4*)&Ql[m * 72 + c8 * 8] = *(const uint4*)&g_qll[((size_t)h * S + i0 + m) * DH + c8 * 8];
    }
    if (tid < 128) {
        qn_s[tid] = g_qn[h * S + i0 + tid];
        minv[tid] = 0x7F800000u;
    }
    __syncthreads();

    uint32_t qh_b = smem_u32(Qh), ql_b = smem_u32(Ql);
    uint32_t bh_b = smem_u32(Bh), bl_b = smem_u32(Bl);
    int lm = lane & 15, lh = lane >> 4;

    const __half* kThp = g_kTh + (size_t)h * DH * S;
    const __half* kTlp = g_kTl + (size_t)h * DH * S;

    float rmin[16];
#pragma unroll
    for (int i = 0; i < 16; i++) rmin[i] = 3.4e38f;

    // ---------------- phase 1: hi-only dist, track row mins -----------------------
    for (int j0 = 0; j0 < S; j0 += 128) {
#pragma unroll
        for (int e = 0; e < 4; e++) {
            int idx = tid + 256 * e;
            int kb = idx >> 4, c16 = idx & 15;
            *(uint4*)&Bh[kb * 136 + c16 * 8] = *(const uint4*)&kThp[(size_t)kb * S + j0 + c16 * 8];
        }
        if (tid < 128) kn_s[tid] = g_kn[h * S + j0 + tid];
        __syncthreads();

        uint32_t bf[4][4];
#pragma unroll
        for (int k4 = 0; k4 < 4; k4++)
            ldm_x4_trans(bf[k4], bh_b + ((k4 * 16 + lm) * 136 + wid * 16 + lh * 8) * 2);

#pragma unroll
        for (int mt = 0; mt < 8; mt++) {
            float a0[4] = {0.f, 0.f, 0.f, 0.f}, a1[4] = {0.f, 0.f, 0.f, 0.f};
#pragma unroll
            for (int k4 = 0; k4 < 4; k4++) {
                uint32_t a[4];
                ldm_x4(a, qh_b + ((mt * 16 + lm) * 72 + k4 * 16 + lh * 8) * 2);
                mma16816(a0, a, bf[k4][0], bf[k4][1]);
                mma16816(a1, a, bf[k4][2], bf[k4][3]);
            }
            int r = mt * 16 + (lane >> 2);
            float qn0 = qn_s[r], qn1 = qn_s[r + 8];
            int cb = wid * 16 + (lane & 3) * 2;
            float kn0 = kn_s[cb], kn1 = kn_s[cb + 1], kn8 = kn_s[cb + 8], kn9 = kn_s[cb + 9];
            float d0 = fminf(fminf(qn0 + kn0 - 2.f * a0[0], qn0 + kn1 - 2.f * a0[1]),
                             fminf(qn0 + kn8 - 2.f * a1[0], qn0 + kn9 - 2.f * a1[1]));
            float d1 = fminf(fminf(qn1 + kn0 - 2.f * a0[2], qn1 + kn1 - 2.f * a0[3]),
                             fminf(qn1 + kn8 - 2.f * a1[2], qn1 + kn9 - 2.f * a1[3]));
            rmin[mt * 2] = fminf(rmin[mt * 2], d0);
            rmin[mt * 2 + 1] = fminf(rmin[mt * 2 + 1], d1);
        }
        __syncthreads();
    }
#pragma unroll
    for (int i = 0; i < 16; i++) {
        rmin[i] = fminf(rmin[i], __shfl_xor_sync(0xffffffffu, rmin[i], 1));
        rmin[i] = fminf(rmin[i], __shfl_xor_sync(0xffffffffu, rmin[i], 2));
    }
    if ((lane & 3) == 0) {
#pragma unroll
        for (int mt = 0; mt < 8; mt++) {
            atomicMin(&minv[mt * 16 + (lane >> 2)], __float_as_uint(fmaxf(rmin[mt * 2], 0.f)));
            atomicMin(&minv[mt * 16 + (lane >> 2) + 8], __float_as_uint(fmaxf(rmin[mt * 2 + 1], 0.f)));
        }
    }
    __syncthreads();
    if (tid < 128)
        g_scale[h * S + i0 + tid] = __expf(-__uint_as_float(minv[tid]) * inv);

    // ---------------- phase 2: split dist, exp -> Kh fp16 -------------------------
    for (int j0 = 0; j0 < S; j0 += 128) {
#pragma unroll
        for (int e = 0; e < 4; e++) {
            int idx = tid + 256 * e;
            int kb = idx >> 4, c16 = idx & 15;
            *(uint4*)&Bh[kb * 136 + c16 * 8] = *(const uint4*)&kThp[(size_t)kb * S + j0 + c16 * 8];
            *(uint4*)&Bl[kb * 136 + c16 * 8] = *(const uint4*)&kTlp[(size_t)kb * S + j0 + c16 * 8];
        }
        if (tid < 128) kn_s[tid] = g_kn[h * S + j0 + tid];
        __syncthreads();

        uint32_t bfh[4][4], bfl[4][4];
#pragma unroll
        for (int k4 = 0; k4 < 4; k4++) {
            ldm_x4_trans(bfh[k4], bh_b + ((k4 * 16 + lm) * 136 + wid * 16 + lh * 8) * 2);
            ldm_x4_trans(bfl[k4], bl_b + ((k4 * 16 + lm) * 136 + wid * 16 + lh * 8) * 2);
        }

#pragma unroll
        for (int mt = 0; mt < 8; mt++) {
            float a0[4] = {0.f, 0.f, 0.f, 0.f}, a1[4] = {0.f, 0.f, 0.f, 0.f};
#pragma unroll
            for (int k4 = 0; k4 < 4; k4++) {
                uint32_t ah[4], al[4];
                ldm_x4(ah, qh_b + ((mt * 16 + lm) * 72 + k4 * 16 + lh * 8) * 2);
                ldm_x4(al, ql_b + ((mt * 16 + lm) * 72 + k4 * 16 + lh * 8) * 2);
                mma16816(a0, ah, bfh[k4][0], bfh[k4][1]);
                mma16816(a0, ah, bfl[k4][0], bfl[k4][1]);
                mma16816(a0, al, bfh[k4][0], bfh[k4][1]);
                mma16816(a1, ah, bfh[k4][2], bfh[k4][3]);
                mma16816(a1, ah, bfl[k4][2], bfl[k4][3]);
                mma16816(a1, al, bfh[k4][2], bfh[k4][3]);
            }
            int r = mt * 16 + (lane >> 2);
            float qn0 = qn_s[r], qn1 = qn_s[r + 8];
            float dm0 = __uint_as_float(minv[r]), dm1 = __uint_as_float(minv[r + 8]);
            int cb = wid * 16 + (lane & 3) * 2;
            float kn0 = kn_s[cb], kn1 = kn_s[cb + 1], kn8 = kn_s[cb + 8], kn9 = kn_s[cb + 9];
            float e00 = __expf((dm0 - fmaxf(qn0 + kn0 - 2.f * a0[0], 0.f)) * inv);
            float e01 = __expf((dm0 - fmaxf(qn0 + kn1 - 2.f * a0[1], 0.f)) * inv);
            float e10 = __expf((dm1 - fmaxf(qn1 + kn0 - 2.f * a0[2], 0.f)) * inv);
            float e11 = __expf((dm1 - fmaxf(qn1 + kn1 - 2.f * a0[3], 0.f)) * inv);
            float f00 = __expf((dm0 - fmaxf(qn0 + kn8 - 2.f * a1[0], 0.f)) * inv);
            float f01 = __expf((dm0 - fmaxf(qn0 + kn9 - 2.f * a1[1], 0.f)) * inv);
            float f10 = __expf((dm1 - fmaxf(qn1 + kn8 - 2.f * a1[2], 0.f)) * inv);
            float f11 = __expf((dm1 - fmaxf(qn1 + kn9 - 2.f * a1[3], 0.f)) * inv);
            __half* Kp0 = &g_Kh[((size_t)(h * S + i0 + r)) * S + j0 + cb];
            __half* Kp1 = Kp0 + (size_t)8 * S;
            *(__half2*)Kp0 = __halves2half2(__float2half(e00), __float2half(e01));
            *(__half2*)(Kp0 + 8) = __halves2half2(__float2half(f00), __float2half(f01));
            *(__half2*)Kp1 = __halves2half2(__float2half(e10), __float2half(e11));
            *(__half2*)(Kp1 + 8) = __halves2half2(__float2half(f10), __float2half(f11));
        }
        __syncthreads();
    }
}

// ---------------- diag_p from exact fp32 (q-k)^2 ----------------------------------
__global__ void diag_kernel(const float* __restrict__ diag_scale,
                            const float* __restrict__ reg_p,
                            const float* __restrict__ bw_p) {
    int gw = (blockIdx.x * blockDim.x + threadIdx.x) >> 5;
    int lane = threadIdx.x & 31;
    if (gw >= H * S) return;
    const float* qp = g_q + (size_t)gw * DH;
    const float* kp = g_k + (size_t)gw * DH;
    float d0 = qp[lane] - kp[lane], d1 = qp[lane + 32] - kp[lane + 32];
    float sum = d0 * d0 + d1 * d1;
#pragma unroll
    for (int o = 16; o > 0; o >>= 1) sum += __shfl_xor_sync(0xffffffffu, sum, o);
    if (lane == 0) {
        float bw = softplusf(bw_p[0]) + 1e-6f;
        float inv = 1.0f / (2.0f * bw * bw);
        float kd = __expf(-sum * inv);
        g_diagp[gw] = softplusf(kd) * diag_scale[gw / S] + reg_p[0];
    }
}

// ---------------- U[h,s,r] = sum_rp pos[s,rp] * proj[h,rp,r] ----------------------
__global__ void u_kernel(const float* __restrict__ pos, const float* __restrict__ proj) {
    __shared__ float pr[RANK][RANK];
    int h = blockIdx.y;
    int tid = threadIdx.x;
    pr[tid >> 4][tid & 15] = proj[h * RANK * RANK + tid];
    __syncthreads();
    int s = blockIdx.x * 256 + tid;
    float pe[RANK];
#pragma unroll
    for (int r = 0; r < RANK; r++) pe[r] = pos[(size_t)s * RANK + r];
#pragma unroll
    for (int r = 0; r < RANK; r++) {
        float acc = 0.f;
#pragma unroll
        for (int rp = 0; rp < RANK; rp++) acc += pe[rp] * pr[rp][r];
        g_U[((size_t)h * S + s) * RANK + r] = acc;
    }
}

// ---------------- alpha = 0; r = v -------------------------------------------------
__global__ void init_kernel() {
    int i = blockIdx.x * blockDim.x + threadIdx.x;
    if (i < H * S * DH) {
        g_alpha[i] = 0.0f;
        g_r[i] = g_v[i];
    }
}

// == HMMA K@alpha (cp.async double-buffered) =======================================
// mode0: r = v - scale*K'a - lam*a;   mode1: store NORMALIZED K'a hi/lo
__global__ void __launch_bounds__(256) kapply_mma(int mode, const float* __restrict__ lam_p) {
    extern __shared__ __align__(16) char sm[];
    uint32_t base = smem_u32(sm);
    // buffers: Ks[2] @ 0 / 18432 (128x72 fp16), Al[2] @ 36864 / 46080 (64x72 fp16)
    uint32_t ksb0 = base, ksb1 = base + 18432;
    uint32_t alb0 = base + 36864, alb1 = base + 46080;

    int tid = threadIdx.x, wid = tid >> 5, lane = tid & 31;
    int h = blockIdx.y;
    int s0 = blockIdx.x * 128;

    const __half* Kb = g_Kh + ((size_t)h * S + s0) * S;
    const __half* Ab = g_alphaH + (size_t)h * S * DH;

    float acc[8][4];
#pragma unroll
    for (int i = 0; i < 8; i++)
#pragma unroll
        for (int j = 0; j < 4; j++) acc[i][j] = 0.f;

    int lm = lane & 15, lh = lane >> 4;
    int mA = tid >> 3, c8A = tid & 7;       // per-thread load coords

    // prefetch chunk 0 into buffer 0
    {
        int t0 = 0;
#pragma unroll
        for (int e = 0; e < 4; e++) {
            int m = mA + 32 * e;
            cp_async16(ksb0 + (uint32_t)(m * 144 + c8A * 16), Kb + (size_t)m * S + t0 + c8A * 8);
        }
#pragma unroll
        for (int e = 0; e < 2; e++) {
            int t = mA + 32 * e;
            cp_async16(alb0 + (uint32_t)(t * 144 + c8A * 16), Ab + (size_t)(t0 + t) * DH + c8A * 8);
        }
        asm volatile("cp.async.commit_group;" ::: "memory");
    }

    for (int c = 0; c < 32; c++) {
        uint32_t ks_cur = (c & 1) ? ksb1 : ksb0;
        uint32_t al_cur = (c & 1) ? alb1 : alb0;
        if (c < 31) {
            uint32_t ks_nxt = (c & 1) ? ksb0 : ksb1;
            uint32_t al_nxt = (c & 1) ? alb0 : alb1;
            int t0 = (c + 1) * 64;
#pragma unroll
            for (int e = 0; e < 4; e++) {
                int m = mA + 32 * e;
                cp_async16(ks_nxt + (uint32_t)(m * 144 + c8A * 16), Kb + (size_t)m * S + t0 + c8A * 8);
            }
#pragma unroll
            for (int e = 0; e < 2; e++) {
                int t = mA + 32 * e;
                cp_async16(al_nxt + (uint32_t)(t * 144 + c8A * 16), Ab + (size_t)(t0 + t) * DH + c8A * 8);
            }
            asm volatile("cp.async.commit_group;" ::: "memory");
            asm volatile("cp.async.wait_group 1;" ::: "memory");
        } else {
            asm volatile("cp.async.wait_group 0;" ::: "memory");
        }
        __syncthreads();

#pragma unroll
        for (int kk = 0; kk < 64; kk += 16) {
            uint32_t a[4];
            ldm_x4(a, ks_cur + (uint32_t)(((wid * 16 + lm) * 72 + kk + lh * 8) * 2));
#pragma unroll
            for (int nt = 0; nt < 4; nt++) {
                uint32_t b[4];
                ldm_x4_trans(b, al_cur + (uint32_t)(((kk + lm) * 72 + nt * 16 + lh * 8) * 2));
                mma16816(acc[nt * 2 + 0], a, b[0], b[1]);
                mma16816(acc[nt * 2 + 1], a, b[2], b[3]);
            }
        }
        __syncthreads();
    }

    float lam = 0.f;
    if (mode == 0) lam = softplusf(lam_p[0]);
    int rbase = s0 + wid * 16 + (lane >> 2);
    float sc0 = g_scale[h * S + rbase];
    float sc1 = g_scale[h * S + rbase + 8];
#pragma unroll
    for (int nt = 0; nt < 8; nt++) {
        int col = nt * 8 + (lane & 3) * 2;
        size_t g0 = ((size_t)h * S + rbase) * DH + col;
        size_t g1 = g0 + 8 * DH;
        if (mode == 0) {
            float2 v0 = *(const float2*)&g_v[g0];
            float2 v1 = *(const float2*)&g_v[g1];
            float2 a0 = *(const float2*)&g_alpha[g0];
            float2 a1 = *(const float2*)&g_alpha[g1];
            *(float2*)&g_r[g0] = make_float2(v0.x - sc0 * acc[nt][0] - lam * a0.x,
                                             v0.y - sc0 * acc[nt][1] - lam * a0.y);
            *(float2*)&g_r[g1] = make_float2(v1.x - sc1 * acc[nt][2] - lam * a1.x,
                                             v1.y - sc1 * acc[nt][3] - lam * a1.y);
        } else {
            float c00 = acc[nt][0], c01 = acc[nt][1];
            float c10 = acc[nt][2], c11 = acc[nt][3];
            __half h00 = __float2half(c00), h01 = __float2half(c01);
            __half h10 = __float2half(c10), h11 = __float2half(c11);
            *(__half2*)&g_ctxH[g0] = __halves2half2(h00, h01);
            *(__half2*)&g_ctxH[g1] = __halves2half2(h10, h11);
            *(__half2*)&g_ctxL[g0] = __halves2half2(__float2half(c00 - __half2float(h00)),
                                                    __float2half(c01 - __half2float(h01)));
            *(__half2*)&g_ctxL[g1] = __halves2half2(__float2half(c10 - __half2float(h10)),
                                                    __float2half(c11 - __half2float(h11)));
        }
    }
}

// ---------------- utr_part[p,h,r,d] = sum_{s in part} U[h,s,r] * r[h,s,d] ---------
__global__ void utr_kernel() {
    int h = blockIdx.x;
    int part = blockIdx.y;
    int tid = threadIdx.x;
    int d = tid & 63, rr = tid >> 6;
    const float* Ub = g_U + (size_t)h * S * RANK;
    const float* rb = g_r + (size_t)h * S * DH;
    int s0 = part * (S / 8);
    float a0 = 0, a1 = 0, a2 = 0, a3 = 0;
    for (int s = s0; s < s0 + S / 8; s += 4) {
        a0 += Ub[(s + 0) * RANK + rr] * rb[(size_t)(s + 0) * DH + d];
        a1 += Ub[(s + 1) * RANK + rr] * rb[(size_t)(s + 1) * DH + d];
        a2 += Ub[(s + 2) * RANK + rr] * rb[(size_t)(s + 2) * DH + d];
        a3 += Ub[(s + 3) * RANK + rr] * rb[(size_t)(s + 3) * DH + d];
    }
    g_utr_part[((part * H + h) * RANK + rr) * DH + d] = (a0 + a1) + (a2 + a3);
}

// ---------------- alpha += r*diag_p + U @ utr; emit fp16 mirror -------------------
__global__ void update_kernel() {
    __shared__ float ut[RANK][DH];
    __shared__ float Us[16][RANK];
    int h = blockIdx.y;
    int tid = threadIdx.x;
    {
        float sum = 0.f;
#pragma unroll
        for (int p = 0; p < 8; p++) sum += g_utr_part[(p * H + h) * RANK * DH + tid];
        ut[tid >> 6][tid & 63] = sum;
    }
    int s0 = blockIdx.x * 16;
    if (tid < 16 * RANK)
        Us[tid >> 4][tid & 15] = g_U[((size_t)h * S + s0 + (tid >> 4)) * RANK + (tid & 15)];
    __syncthreads();

    int sl = tid >> 6;
    int d = tid & 63;
    int s = s0 + sl;
    size_t idx = ((size_t)h * S + s) * DH + d;
    float acc = 0.f;
#pragma unroll
    for (int r2 = 0; r2 < RANK; r2++) acc += Us[sl][r2] * ut[r2][d];
    float na = g_alpha[idx] + g_r[idx] * g_diagp[h * S + s] + acc;
    g_alpha[idx] = na;
    g_alphaH[idx] = __float2half(na);
}

// == output GEMM: out = (scale ⊙ ctxN)_flat @ Wo; per-head-block scale folding =====
__global__ void __launch_bounds__(256) wo_tc(float* __restrict__ out) {
    extern __shared__ __align__(16) char sm[];
    __half* Ah = (__half*)sm;                 // [128][72]
    __half* Alo = (__half*)(sm + 18432);
    __half* Bh = (__half*)(sm + 36864);       // [64][136]
    __half* Bl = (__half*)(sm + 54272);
    float* scs = (float*)(sm + 71680);        // 128 row scales for current head

    int tid = threadIdx.x, lane = tid & 31, wid = tid >> 5;
    int wm = wid >> 1, wn = wid & 1;
    int row0 = blockIdx.y * 128, col0 = blockIdx.x * 128;

    float acc[2][8][4];
#pragma unroll
    for (int i = 0; i < 2; i++)
#pragma unroll
        for (int j = 0; j < 8; j++)
#pragma unroll
            for (int l = 0; l < 4; l++) acc[i][j][l] = 0.f;

    uint32_t ah_b = smem_u32(Ah), al_b = smem_u32(Alo);
    uint32_t bh_b = smem_u32(Bh), bl_b = smem_u32(Bl);
    int lm = lane & 15, lh = lane >> 4;

    for (int ck = 0; ck < 16; ck++) {          // head / k-block
        int k0 = ck * 64;
#pragma unroll
        for (int e = 0; e < 4; e++) {
            int idx = tid + 256 * e;
            int m = idx >> 3, c8 = idx & 7;
            *(uint4*)&Ah[m * 72 + c8 * 8]  = *(const uint4*)&g_ctxH[((size_t)ck * S + row0 + m) * DH + c8 * 8];
            *(uint4*)&Alo[m * 72 + c8 * 8] = *(const uint4*)&g_ctxL[((size_t)ck * S + row0 + m) * DH + c8 * 8];
            int kb = idx >> 4, c16 = idx & 15;
            *(uint4*)&Bh[kb * 136 + c16 * 8] = *(const uint4*)&g_Woh[(size_t)(k0 + kb) * D + col0 + c16 * 8];
            *(uint4*)&Bl[kb * 136 + c16 * 8] = *(const uint4*)&g_Wol[(size_t)(k0 + kb) * D + col0 + c16 * 8];
        }
        if (tid < 128) scs[tid] = g_scale[ck * S + row0 + tid];
        __syncthreads();

        float accp[2][8][4];
#pragma unroll
        for (int i = 0; i < 2; i++)
#pragma unroll
            for (int j = 0; j < 8; j++)
#pragma unroll
                for (int l = 0; l < 4; l++) accp[i][j][l] = 0.f;

#pragma unroll
        for (int kk = 0; kk < 64; kk += 16) {
            uint32_t a_h[2][4], a_l[2][4];
#pragma unroll
            for (int mt = 0; mt < 2; mt++) {
                ldm_x4(a_h[mt], ah_b + ((wm * 32 + mt * 16 + lm) * 72 + kk + lh * 8) * 2);
                ldm_x4(a_l[mt], al_b + ((wm * 32 + mt * 16 + lm) * 72 + kk + lh * 8) * 2);
            }
#pragma unroll
            for (int ng = 0; ng < 4; ng++) {
                uint32_t b_h[4], b_l[4];
                ldm_x4_trans(b_h, bh_b + ((kk + lm) * 136 + wn * 64 + ng * 16 + lh * 8) * 2);
                ldm_x4_trans(b_l, bl_b + ((kk + lm) * 136 + wn * 64 + ng * 16 + lh * 8) * 2);
#pragma unroll
                for (int mt = 0; mt < 2; mt++) {
                    mma16816(accp[mt][ng * 2 + 0], a_h[mt], b_h[0], b_h[1]);
                    mma16816(accp[mt][ng * 2 + 0], a_h[mt], b_l[0], b_l[1]);
                    mma16816(accp[mt][ng * 2 + 0], a_l[mt], b_h[0], b_h[1]);
                    mma16816(accp[mt][ng * 2 + 1], a_h[mt], b_h[2], b_h[3]);
                    mma16816(accp[mt][ng * 2 + 1], a_h[mt], b_l[2], b_l[3]);
                    mma16816(accp[mt][ng * 2 + 1], a_l[mt], b_h[2], b_h[3]);
                }
            }
        }

        // fold with per-row scale of this head block
#pragma unroll
        for (int mt = 0; mt < 2; mt++) {
            int rl = wm * 32 + mt * 16 + (lane >> 2);
            float sc0 = scs[rl], sc1 = scs[rl + 8];
#pragma unroll
            for (int nt = 0; nt < 8; nt++) {
                acc[mt][nt][0] += sc0 * accp[mt][nt][0];
                acc[mt][nt][1] += sc0 * accp[mt][nt][1];
                acc[mt][nt][2] += sc1 * accp[mt][nt][2];
                acc[mt][nt][3] += sc1 * accp[mt][nt][3];
            }
        }
        __syncthreads();
    }

#pragma unroll
    for (int mt = 0; mt < 2; mt++) {
        int r0 = row0 + wm * 32 + mt * 16 + (lane >> 2);
#pragma unroll
        for (int nt = 0; nt < 8; nt++) {
            int c = col0 + wn * 64 + nt * 8 + (lane & 3) * 2;
#pragma unroll
            for (int rr = 0; rr < 2; rr++) {
                int s = r0 + rr * 8;
                *(float2*)&out[(size_t)s * D + c] =
                    make_float2(acc[mt][nt][rr * 2 + 0], acc[mt][nt][rr * 2 + 1]);
            }
        }
    }
}

// ---------------- launch ----------------------------------------------------------
extern "C" void kernel_launch(void* const* d_in, const int* in_sizes, int n_in,
                              void* d_out, int out_size) {
    const float* x          = (const float*)d_in[0];
    const float* Wq         = (const float*)d_in[1];
    const float* Wk         = (const float*)d_in[2];
    const float* Wv         = (const float*)d_in[3];
    const float* Wo         = (const float*)d_in[4];
    const float* bandwidth  = (const float*)d_in[5];
    const float* diag_scale = (const float*)d_in[6];
    const float* pos        = (const float*)d_in[7];
    const float* proj       = (const float*)d_in[8];
    const float* reg        = (const float*)d_in[9];
    const float* lam        = (const float*)d_in[10];
    float* out = (float*)d_out;

    static bool attr_done = false;
    if (!attr_done) {
        cudaFuncSetAttribute(qkv_tc, cudaFuncAttributeMaxDynamicSharedMemorySize, 71680);
        cudaFuncSetAttribute(wo_tc, cudaFuncAttributeMaxDynamicSharedMemorySize, 72192);
        cudaFuncSetAttribute(kmat_tc, cudaFuncAttributeMaxDynamicSharedMemorySize, 73216);
        cudaFuncSetAttribute(kapply_mma, cudaFuncAttributeMaxDynamicSharedMemorySize, 55296);
        attr_done = true;
    }

    const int NTOT = S * D + 4 * D * D;
    cvt_all<<<(NTOT + 255) / 256, 256>>>(x, Wq, Wk, Wv, Wo);

    qkv_tc<<<dim3(D / 128, S / 128, 3), 256, 71680>>>();
    norms_kernel<<<(2 * H * S * 32 + 255) / 256, 256>>>();
    transpose_k<<<dim3(S / 32, DH / 32, H), dim3(32, 8)>>>();
    kmat_tc<<<dim3(S / 128, H), 256, 73216>>>(bandwidth);
    diag_kernel<<<(H * S * 32 + 255) / 256, 256>>>(diag_scale, reg, bandwidth);
    u_kernel<<<dim3(S / 256, H), 256>>>(pos, proj);

    // Richardson iteration 1: alpha = 0 => r = v
    init_kernel<<<(H * S * DH + 255) / 256, 256>>>();
    utr_kernel<<<dim3(H, 8), 1024>>>();
    update_kernel<<<dim3(S / 16, H), 1024>>>();

    for (int it = 1; it < 5; it++) {
        kapply_mma<<<dim3(S / 128, H), 256, 55296>>>(0, lam);
        utr_kernel<<<dim3(H, 8), 1024>>>();
        update_kernel<<<dim3(S / 16, H), 1024>>>();
    }

    kapply_mma<<<dim3(S / 128, H), 256, 55296>>>(1, lam);
    wo_tc<<<dim3(D / 128, S / 128), 256, 72192>>>(out);
}